// round 6
// baseline (speedup 1.0000x reference)
#include <cuda_runtime.h>
#include <cstdint>

#define B_  8
#define C_  256
#define N_  4096
#define CQ_ 32
#define TQ  128
#define TJ  64
#define NT  (N_ / TJ)

#define LOG2E 1.4426950408889634f
#define SHIFT2 23.083088886526f   /* 16 * log2e */

typedef unsigned long long ull;

// ---------------- scratch ----------------
__device__ float g_qhi[B_ * N_ * CQ_];
__device__ float g_qlo[B_ * N_ * CQ_];
__device__ float g_khi[B_ * N_ * CQ_];
__device__ float g_klo[B_ * N_ * CQ_];
__device__ float g_v  [B_ * C_ * N_];     // [B][C][N]

// ---------------- PTX helpers ----------------
__device__ __forceinline__ uint32_t su32(const void* p) {
    uint32_t a;
    asm("{ .reg .u64 t; cvta.to.shared.u64 t, %1; cvt.u32.u64 %0, t; }" : "=r"(a) : "l"(p));
    return a;
}
__device__ __forceinline__ float tf32r(float x) {
    uint32_t u;
    asm("cvt.rna.tf32.f32 %0, %1;" : "=r"(u) : "f"(x));
    return __uint_as_float(u);
}
__device__ __forceinline__ uint32_t tf32u(float x) {
    uint32_t u;
    asm("cvt.rna.tf32.f32 %0, %1;" : "=r"(u) : "f"(x));
    return u;
}
__device__ __forceinline__ float ex2f(float x) {
    float y;
    asm("ex2.approx.ftz.f32 %0, %1;" : "=f"(y) : "f"(x));
    return y;
}
__device__ __forceinline__ void cpa16(uint32_t dst, const void* src) {
    asm volatile("cp.async.cg.shared.global [%0], [%1], 16;" :: "r"(dst), "l"(src));
}
#define CP_COMMIT() asm volatile("cp.async.commit_group;" ::: "memory")
#define CP_WAIT0()  asm volatile("cp.async.wait_group 0;" ::: "memory")
#define CP_WAIT1()  asm volatile("cp.async.wait_group 1;" ::: "memory")

__device__ __forceinline__ void lds64(uint32_t& a, uint32_t& b, uint32_t addr) {
    asm volatile("ld.shared.v2.u32 {%0, %1}, [%2];" : "=r"(a), "=r"(b) : "r"(addr));
}
__device__ __forceinline__ void mma_tf32(float* c, uint32_t a0, uint32_t a1,
                                         uint32_t a2, uint32_t a3,
                                         uint32_t b0, uint32_t b1) {
    asm volatile(
        "mma.sync.aligned.m16n8k8.row.col.f32.tf32.tf32.f32 "
        "{%0,%1,%2,%3}, {%4,%5,%6,%7}, {%8,%9}, {%0,%1,%2,%3};"
        : "+f"(c[0]), "+f"(c[1]), "+f"(c[2]), "+f"(c[3])
        : "r"(a0), "r"(a1), "r"(a2), "r"(a3), "r"(b0), "r"(b1));
}

// interleaved channel slot (fragments load as LDS.64 pairs)
__device__ __host__ __forceinline__ int ilvpos(int d) {
    int e = d & 7;
    int p = (e < 4) ? 2 * e : 2 * (e - 4) + 1;
    return (d & ~7) | p;
}

// ---------------- packed f32x2 (proj) ----------------
__device__ __forceinline__ ull ffma2(ull a, ull b, ull c) {
    ull d; asm("fma.rn.f32x2 %0, %1, %2, %3;" : "=l"(d) : "l"(a), "l"(b), "l"(c)); return d;
}
__device__ __forceinline__ ull pack2(float x, float y) {
    ull r; asm("mov.b64 %0, {%1, %2};" : "=l"(r) : "f"(x), "f"(y)); return r;
}
__device__ __forceinline__ float2 unpack2(ull v) {
    float2 f; asm("mov.b64 {%0, %1}, %2;" : "=f"(f.x), "=f"(f.y) : "l"(v)); return f;
}

// ====================================================================
// Projection kernel. Q is pre-scaled by log2e before hi/lo split.
// ====================================================================
#define PROJ_SMEM_FLOATS (2048 + 32*258 + 32*36 + 32*36)
#define PROJ_SMEM_BYTES  (PROJ_SMEM_FLOATS * 4)

__global__ void __launch_bounds__(256) proj_kernel(
    const float* __restrict__ x,
    const float* __restrict__ wq, const float* __restrict__ bq,
    const float* __restrict__ wk, const float* __restrict__ bk,
    const float* __restrict__ wv, const float* __restrict__ bv)
{
    extern __shared__ float sm[];
    float* xs  = sm;
    float* wvs = sm + 2048;
    float* wqs = wvs + 32 * 258;
    float* wks = wqs + 32 * 36;

    const int tid = threadIdx.x;
    const int n   = tid & 63;
    const int grp = tid >> 6;
    const int b   = blockIdx.y;
    const int n0  = blockIdx.x * 64;

    ull accv[32]; ull accq[4], acck[4];
#pragma unroll
    for (int i = 0; i < 32; i++) accv[i] = 0ull;
#pragma unroll
    for (int i = 0; i < 4; i++) { accq[i] = 0ull; acck[i] = 0ull; }

    for (int kc = 0; kc < 8; kc++) {
        __syncthreads();
        {
            const float4* xg = (const float4*)(x + ((size_t)b * C_ + kc * 32) * N_ + n0);
            float4* xs4 = (float4*)xs;
            for (int i = tid; i < 32 * 16; i += 256) {
                int ci = i >> 4, n4 = i & 15;
                xs4[ci * 16 + n4] = xg[(size_t)ci * (N_ / 4) + n4];
            }
        }
        for (int i = tid; i < 256 * 32; i += 256) {
            int co = i >> 5, ci = i & 31;
            wvs[ci * 258 + co] = wv[co * C_ + kc * 32 + ci];
        }
        for (int i = tid; i < 32 * 32; i += 256) {
            int d = i >> 5, ci = i & 31;
            wqs[ci * 36 + d] = wq[d * C_ + kc * 32 + ci];
            wks[ci * 36 + d] = wk[d * C_ + kc * 32 + ci];
        }
        __syncthreads();

#pragma unroll 4
        for (int ci = 0; ci < 32; ci++) {
            float xv = xs[ci * 64 + n];
            ull  xv2 = pack2(xv, xv);
            const ull* wr  = (const ull*)&wvs[ci * 258 + grp * 64];
#pragma unroll
            for (int i = 0; i < 32; i++) accv[i] = ffma2(wr[i], xv2, accv[i]);
            const ull* wrq = (const ull*)&wqs[ci * 36 + grp * 8];
            const ull* wrk = (const ull*)&wks[ci * 36 + grp * 8];
#pragma unroll
            for (int i = 0; i < 4; i++) {
                accq[i] = ffma2(wrq[i], xv2, accq[i]);
                acck[i] = ffma2(wrk[i], xv2, acck[i]);
            }
        }
    }

    const size_t ng = (size_t)b * N_ + n0 + n;
    {
        const size_t vbase = ((size_t)b * C_) * N_ + n0 + n;
#pragma unroll
        for (int i = 0; i < 32; i++) {
            float2 a = unpack2(accv[i]);
            int c0 = grp * 64 + 2 * i;
            g_v[vbase + (size_t)c0 * N_]       = tf32r(a.x + __ldg(&bv[c0]));
            g_v[vbase + (size_t)(c0 + 1) * N_] = tf32r(a.y + __ldg(&bv[c0 + 1]));
        }
    }
    {
        float* qh = g_qhi + ng * CQ_; float* ql = g_qlo + ng * CQ_;
        float* kh = g_khi + ng * CQ_; float* kl = g_klo + ng * CQ_;
#pragma unroll
        for (int i = 0; i < 4; i++) {
            float2 a = unpack2(accq[i]);
            int d0 = grp * 8 + 2 * i;
            int p0 = ilvpos(d0), p1 = ilvpos(d0 + 1);
            float v0 = (a.x + __ldg(&bq[d0]))     * LOG2E;   // log2-domain Q
            float v1 = (a.y + __ldg(&bq[d0 + 1])) * LOG2E;
            float h0 = tf32r(v0), h1 = tf32r(v1);
            qh[p0] = h0; qh[p1] = h1;
            ql[p0] = tf32r(v0 - h0); ql[p1] = tf32r(v1 - h1);
            a = unpack2(acck[i]);
            v0 = a.x + __ldg(&bk[d0]);
            v1 = a.y + __ldg(&bk[d0 + 1]);
            h0 = tf32r(v0); h1 = tf32r(v1);
            kh[p0] = h0; kh[p1] = h1;
            kl[p0] = tf32r(v0 - h0); kl[p1] = tf32r(v1 - h1);
        }
    }
}

// ====================================================================
// mma.sync flash attention, 512 threads / 16 warps (8 qw x 2 cg).
// Register diet: Q-lo fragments are NOT register-resident — reloaded
// from SMEM per key-group. Dual S accumulator chains. ex2 softmax.
// ====================================================================
#define O_V0   0
#define O_V1   16384
#define O_KH0  32768
#define O_KL0  34816
#define O_KH1  36864
#define O_KL1  38912
#define O_QH   40960
#define O_QL   45056
#define ATTN_SMEM_BYTES (49152 * 4)

__global__ void __launch_bounds__(512, 1) attn_mma(
    const float* __restrict__ x, float* __restrict__ out)
{
    extern __shared__ float sm[];
    const uint32_t sb = su32(sm);
    const int tid = threadIdx.x;
    const int w   = tid >> 5;
    const int qw  = w & 7;
    const int cg  = w >> 3;
    const int l   = tid & 31;
    const int l4  = l >> 2;
    const int t   = l & 3;
    const int b   = blockIdx.y;
    const int q0  = blockIdx.x * TQ;

    const int xorc = 8 * (l4 & 3);

    // ---------------- prologue: Q + tile 0 ----------------
    for (int idx = tid; idx < 1024; idx += 512) {
        int r = idx >> 3, sc = idx & 7;
        uint32_t dst = (uint32_t)(r * 32 + ((4 * sc) ^ (8 * (r & 3))));
        const size_t src = ((size_t)(b * N_ + q0 + r)) * CQ_ + sc * 4;
        cpa16(sb + (O_QH + dst) * 4, &g_qhi[src]);
        cpa16(sb + (O_QL + dst) * 4, &g_qlo[src]);
    }
    for (int idx = tid; idx < 512; idx += 512) {
        int r = idx >> 3, sc = idx & 7;
        uint32_t dst = (uint32_t)(r * 32 + ((4 * sc) ^ (8 * (r & 3))));
        const size_t src = ((size_t)(b * N_ + r)) * CQ_ + sc * 4;
        cpa16(sb + (O_KH0 + dst) * 4, &g_khi[src]);
        cpa16(sb + (O_KL0 + dst) * 4, &g_klo[src]);
    }
    for (int idx = tid; idx < 4096; idx += 512) {
        int c = idx >> 4, jc = idx & 15;
        uint32_t dst = (uint32_t)(c * 64 + ((4 * jc) ^ (8 * (c & 3))));
        cpa16(sb + (O_V0 + dst) * 4, &g_v[((size_t)(b * C_) + c) * N_ + jc * 4]);
    }
    CP_COMMIT();
    CP_WAIT0();
    __syncthreads();

    // Q-hi fragments resident; Q-lo base address only
    uint32_t qh[4][4];
    const uint32_t qlb = sb + (O_QL + (16 * qw + l4) * 32) * 4;
    {
        const int rq = 16 * qw + l4;
#pragma unroll
        for (int g = 0; g < 4; g++) {
            uint32_t sx = (uint32_t)((8 * g + 2 * t) ^ xorc);
            uint32_t a0 = sb + (O_QH + rq * 32 + sx) * 4;
            lds64(qh[g][0], qh[g][2], a0);
            lds64(qh[g][1], qh[g][3], a0 + 8 * 32 * 4);
        }
    }

    float o[16][4];
#pragma unroll
    for (int i = 0; i < 16; i++)
#pragma unroll
        for (int e = 0; e < 4; e++) o[i][e] = 0.f;
    float ls0 = 0.f, ls1 = 0.f;

    const uint32_t sxg[4] = { (uint32_t)((0  + 2 * t) ^ xorc), (uint32_t)((8  + 2 * t) ^ xorc),
                              (uint32_t)((16 + 2 * t) ^ xorc), (uint32_t)((24 + 2 * t) ^ xorc) };

    for (int tt = 0; tt < NT; tt++) {
        __syncthreads();
        if (tt + 1 < NT) {
            const int j1 = (tt + 1) * TJ;
            const uint32_t kh_d = (tt + 1) & 1 ? O_KH1 : O_KH0;
            const uint32_t kl_d = (tt + 1) & 1 ? O_KL1 : O_KL0;
            const uint32_t v_d  = (tt + 1) & 1 ? O_V1  : O_V0;
            {
                int r = tid >> 3, sc = tid & 7;
                if (tid < 512) {
                    uint32_t dst = (uint32_t)(r * 32 + ((4 * sc) ^ (8 * (r & 3))));
                    const size_t src = ((size_t)(b * N_ + j1 + r)) * CQ_ + sc * 4;
                    cpa16(sb + (kh_d + dst) * 4, &g_khi[src]);
                    cpa16(sb + (kl_d + dst) * 4, &g_klo[src]);
                }
            }
            for (int idx = tid; idx < 4096; idx += 512) {
                int c = idx >> 4, jc = idx & 15;
                uint32_t dst = (uint32_t)(c * 64 + ((4 * jc) ^ (8 * (c & 3))));
                cpa16(sb + (v_d + dst) * 4, &g_v[((size_t)(b * C_) + c) * N_ + j1 + jc * 4]);
            }
            CP_COMMIT();
            CP_WAIT1();
        } else {
            CP_WAIT0();
        }
        __syncthreads();

        const uint32_t khb = sb + ((tt & 1) ? O_KH1 : O_KH0) * 4;
        const uint32_t klb = sb + ((tt & 1) ? O_KL1 : O_KL0) * 4;
        const uint32_t vb  = sb + ((tt & 1) ? O_V1  : O_V0 ) * 4;

#pragma unroll
        for (int kg = 0; kg < 8; kg++) {
            // ---- S fragment for this 8-key group (dual accumulation chains) ----
            float sA[4] = {0.f, 0.f, 0.f, 0.f};
            float sB[4] = {0.f, 0.f, 0.f, 0.f};
            const uint32_t krow = (uint32_t)((8 * kg + l4) * 32) * 4;
#pragma unroll
            for (int g = 0; g < 4; g++) {
                uint32_t bh0, bh1, bl0, bl1, l0, l1, l2, l3;
                lds64(bh0, bh1, khb + krow + sxg[g] * 4);
                lds64(bl0, bl1, klb + krow + sxg[g] * 4);
                lds64(l0, l2, qlb + sxg[g] * 4);               // Q-lo frag (kg-invariant, reloaded)
                lds64(l1, l3, qlb + sxg[g] * 4 + 1024);
                mma_tf32(sA, qh[g][0], qh[g][1], qh[g][2], qh[g][3], bh0, bh1);
                mma_tf32(sB, l0, l1, l2, l3, bh0, bh1);
                mma_tf32(sA, qh[g][0], qh[g][1], qh[g][2], qh[g][3], bl0, bl1);
            }
            // ---- softmax (log2 domain, fixed shift) ----
            uint32_t pu[4];
#pragma unroll
            for (int e = 0; e < 4; e++) {
                float p = ex2f((sA[e] + sB[e]) - SHIFT2);
                uint32_t u = tf32u(p);
                if (e < 2) ls0 += __uint_as_float(u); else ls1 += __uint_as_float(u);
                pu[e] = u;
            }
            // ---- PV for this key group (C-frag -> A-frag reorder c0,c2,c1,c3) ----
            const uint32_t a0 = pu[0], a1 = pu[2], a2 = pu[1], a3 = pu[3];
            uint32_t addr = vb + (uint32_t)(cg * 8192 + l4 * 64 + ((8 * kg + 2 * t) ^ xorc)) * 4;
#pragma unroll
            for (int nt2 = 0; nt2 < 16; nt2++) {
                uint32_t b0, b1;
                lds64(b0, b1, addr);
                mma_tf32(o[nt2], a0, a1, a2, a3, b0, b1);
                addr += 512 * 4;
            }
        }
    }

    // ---------------- epilogue ----------------
    ls0 += __shfl_xor_sync(0xffffffffu, ls0, 1);
    ls0 += __shfl_xor_sync(0xffffffffu, ls0, 2);
    ls1 += __shfl_xor_sync(0xffffffffu, ls1, 1);
    ls1 += __shfl_xor_sync(0xffffffffu, ls1, 2);
    const float inv0 = 1.0f / ls0;
    const float inv1 = 1.0f / ls1;

    float* stage = sm + O_V0;
    const int qlr = 16 * qw + l4;
#pragma unroll 1
    for (int ch = 0; ch < 4; ch++) {
        __syncthreads();
        if (cg == (ch >> 1)) {
#pragma unroll
            for (int k = 0; k < 8; k++) {
                const int nt2 = (ch & 1) * 8 + k;
                const int cloc = k * 8 + 2 * t;
                stage[cloc * 132 + qlr]           = o[nt2][0] * inv0;
                stage[(cloc + 1) * 132 + qlr]     = o[nt2][1] * inv0;
                stage[cloc * 132 + qlr + 8]       = o[nt2][2] * inv1;
                stage[(cloc + 1) * 132 + qlr + 8] = o[nt2][3] * inv1;
            }
        }
        __syncthreads();
        const int cloc2 = tid & 63;
        const int seg   = tid >> 6;
        const int cglob = ch * 64 + cloc2;
        const size_t gbase = ((size_t)(b * C_ + cglob)) * N_ + q0 + seg * 16;
        const float4* xs4 = (const float4*)(x + gbase);
        float4* os4 = (float4*)(out + gbase);
        const float* srow = stage + cloc2 * 132 + seg * 16;
#pragma unroll
        for (int i = 0; i < 4; i++) {
            float4 v = *(const float4*)(srow + 4 * i);
            float4 xv = xs4[i];
            float4 r;
            r.x = xv.x + v.x; r.y = xv.y + v.y; r.z = xv.z + v.z; r.w = xv.w + v.w;
            os4[i] = r;
        }
    }
}

// ====================================================================
extern "C" void kernel_launch(void* const* d_in, const int* in_sizes, int n_in,
                              void* d_out, int out_size)
{
    const float* x  = (const float*)d_in[0];
    const float* wq = (const float*)d_in[1];
    const float* bq = (const float*)d_in[2];
    const float* wk = (const float*)d_in[3];
    const float* bk = (const float*)d_in[4];
    const float* wv = (const float*)d_in[5];
    const float* bv = (const float*)d_in[6];
    float* out = (float*)d_out;

    cudaFuncSetAttribute(proj_kernel, cudaFuncAttributeMaxDynamicSharedMemorySize, PROJ_SMEM_BYTES);
    cudaFuncSetAttribute(attn_mma,    cudaFuncAttributeMaxDynamicSharedMemorySize, ATTN_SMEM_BYTES);

    proj_kernel<<<dim3(N_ / 64, B_), 256, PROJ_SMEM_BYTES>>>(x, wq, bq, wk, bk, wv, bv);
    attn_mma<<<dim3(N_ / TQ, B_), 512, ATTN_SMEM_BYTES>>>(x, out);
}

// round 7
// speedup vs baseline: 1.6733x; 1.6733x over previous
#include <cuda_runtime.h>
#include <cuda_fp16.h>
#include <cstdint>

#define B_  8
#define C_  256
#define N_  4096
#define CQ_ 32
#define TQ  128
#define TJ  64
#define NT  (N_ / TJ)

#define LOG2E 1.4426950408889634f

typedef unsigned long long ull;

// ---------------- gmem scratch (proj writes MMA-ready swizzled tiles) ----------------
// g_q: [b][qtile 32][sec 4: hi_g0,hi_g1,lo_g0,lo_g1][row 128][16 halves]  (16KB/qtile)
// g_k: [b][tile 64][sec 4][key 64][16 halves]                            (8KB/tile)
// g_v: [b][tile 64][kg 4][c 256][16 halves]                              (32KB/tile)
__device__ __align__(128) __half g_q[8 * 32 * 4 * 128 * 16];
__device__ __align__(128) __half g_k[8 * 64 * 4 * 64 * 16];
__device__ __align__(128) __half g_v[8 * 64 * 4 * 256 * 16];

// ---------------- PTX helpers ----------------
__device__ __forceinline__ uint32_t su32(const void* p) {
    uint32_t a;
    asm("{ .reg .u64 t; cvta.to.shared.u64 t, %1; cvt.u32.u64 %0, t; }" : "=r"(a) : "l"(p));
    return a;
}
__device__ __forceinline__ float ex2f(float x) {
    float y;
    asm("ex2.approx.ftz.f32 %0, %1;" : "=f"(y) : "f"(x));
    return y;
}
__device__ __forceinline__ void lds64(uint32_t& a, uint32_t& b, uint32_t addr) {
    asm volatile("ld.shared.v2.u32 {%0, %1}, [%2];" : "=r"(a), "=r"(b) : "r"(addr));
}
__device__ __forceinline__ void mma_f16(float* c, uint32_t a0, uint32_t a1,
                                        uint32_t a2, uint32_t a3,
                                        uint32_t b0, uint32_t b1) {
    asm volatile(
        "mma.sync.aligned.m16n8k16.row.col.f32.f16.f16.f32 "
        "{%0,%1,%2,%3}, {%4,%5,%6,%7}, {%8,%9}, {%0,%1,%2,%3};"
        : "+f"(c[0]), "+f"(c[1]), "+f"(c[2]), "+f"(c[3])
        : "r"(a0), "r"(a1), "r"(a2), "r"(a3), "r"(b0), "r"(b1));
}
__device__ __forceinline__ uint32_t packh2(float hi, float lo) {
    uint32_t u;
    asm("cvt.rn.f16x2.f32 %0, %1, %2;" : "=r"(u) : "f"(hi), "f"(lo));
    return u;
}
__device__ __forceinline__ float h2sum(uint32_t u) {  // f16x2 -> f32(lo)+f32(hi)
    float lo, hi;
    asm("{.reg .b16 l, h;\n mov.b32 {l, h}, %2;\n cvt.f32.f16 %0, l;\n cvt.f32.f16 %1, h;}"
        : "=f"(lo), "=f"(hi) : "r"(u));
    return lo + hi;
}
#define MB_INIT(mb, cnt) \
    asm volatile("mbarrier.init.shared.b64 [%0], %1;" :: "r"(mb), "r"(cnt) : "memory")
#define MB_EXPECT(mb, tx) \
    asm volatile("mbarrier.arrive.expect_tx.shared.b64 _, [%0], %1;" :: "r"(mb), "r"(tx) : "memory")
__device__ __forceinline__ void mb_wait(uint32_t mb, uint32_t parity) {
    asm volatile(
        "{\n .reg .pred P;\n"
        "W%=:\n"
        " mbarrier.try_wait.parity.acquire.cta.shared::cta.b64 P, [%0], %1, 0x989680;\n"
        " @P bra D%=;\n"
        " bra W%=;\n"
        "D%=:\n}"
        :: "r"(mb), "r"(parity) : "memory");
}
__device__ __forceinline__ void bulkcp(uint32_t dst, const void* src, uint32_t bytes, uint32_t mbar) {
    asm volatile(
        "cp.async.bulk.shared::cluster.global.mbarrier::complete_tx::bytes [%0], [%1], %2, [%3];"
        :: "r"(dst), "l"(src), "r"(bytes), "r"(mbar) : "memory");
}

// granule interleave: element e (0..15) -> half-slot within 32B granule row
__device__ __forceinline__ int sig(int e) {
    return (e < 8) ? ((e >> 1) * 4 + (e & 1)) : (((e & 7) >> 1) * 4 + 2 + (e & 1));
}

// ---------------- packed f32x2 (proj compute) ----------------
__device__ __forceinline__ ull ffma2(ull a, ull b, ull c) {
    ull d; asm("fma.rn.f32x2 %0, %1, %2, %3;" : "=l"(d) : "l"(a), "l"(b), "l"(c)); return d;
}
__device__ __forceinline__ ull pack2(float x, float y) {
    ull r; asm("mov.b64 %0, {%1, %2};" : "=l"(r) : "f"(x), "f"(y)); return r;
}
__device__ __forceinline__ float2 unpack2(ull v) {
    float2 f; asm("mov.b64 {%0, %1}, %2;" : "=f"(f.x), "=f"(f.y) : "l"(v)); return f;
}

// ====================================================================
// Projection kernel: compute unchanged; stores now write fp16 hi/lo
// Q,K and fp16 V in the bulk-copyable swizzled tile layouts.
// ====================================================================
#define PROJ_SMEM_FLOATS (2048 + 32*258 + 32*36 + 32*36)
#define PROJ_SMEM_BYTES  (PROJ_SMEM_FLOATS * 4)

__global__ void __launch_bounds__(256) proj_kernel(
    const float* __restrict__ x,
    const float* __restrict__ wq, const float* __restrict__ bq,
    const float* __restrict__ wk, const float* __restrict__ bk,
    const float* __restrict__ wv, const float* __restrict__ bv)
{
    extern __shared__ float sm[];
    float* xs  = sm;
    float* wvs = sm + 2048;
    float* wqs = wvs + 32 * 258;
    float* wks = wqs + 32 * 36;

    const int tid = threadIdx.x;
    const int n   = tid & 63;
    const int grp = tid >> 6;
    const int b   = blockIdx.y;
    const int n0  = blockIdx.x * 64;

    ull accv[32]; ull accq[4], acck[4];
#pragma unroll
    for (int i = 0; i < 32; i++) accv[i] = 0ull;
#pragma unroll
    for (int i = 0; i < 4; i++) { accq[i] = 0ull; acck[i] = 0ull; }

    for (int kc = 0; kc < 8; kc++) {
        __syncthreads();
        {
            const float4* xg = (const float4*)(x + ((size_t)b * C_ + kc * 32) * N_ + n0);
            float4* xs4 = (float4*)xs;
            for (int i = tid; i < 32 * 16; i += 256) {
                int ci = i >> 4, n4 = i & 15;
                xs4[ci * 16 + n4] = xg[(size_t)ci * (N_ / 4) + n4];
            }
        }
        for (int i = tid; i < 256 * 32; i += 256) {
            int co = i >> 5, ci = i & 31;
            wvs[ci * 258 + co] = wv[co * C_ + kc * 32 + ci];
        }
        for (int i = tid; i < 32 * 32; i += 256) {
            int d = i >> 5, ci = i & 31;
            wqs[ci * 36 + d] = wq[d * C_ + kc * 32 + ci];
            wks[ci * 36 + d] = wk[d * C_ + kc * 32 + ci];
        }
        __syncthreads();

#pragma unroll 4
        for (int ci = 0; ci < 32; ci++) {
            float xv = xs[ci * 64 + n];
            ull  xv2 = pack2(xv, xv);
            const ull* wr  = (const ull*)&wvs[ci * 258 + grp * 64];
#pragma unroll
            for (int i = 0; i < 32; i++) accv[i] = ffma2(wr[i], xv2, accv[i]);
            const ull* wrq = (const ull*)&wqs[ci * 36 + grp * 8];
            const ull* wrk = (const ull*)&wks[ci * 36 + grp * 8];
#pragma unroll
            for (int i = 0; i < 4; i++) {
                accq[i] = ffma2(wrq[i], xv2, accq[i]);
                acck[i] = ffma2(wrk[i], xv2, acck[i]);
            }
        }
    }

    const int np   = n0 + n;          // position within batch
    const int tile = np >> 6;
    const int j    = np & 63;
    const int qt   = np >> 7;
    const int qr   = np & 127;
    const size_t kBase = ((size_t)(b * 64 + tile)) << 12;   // *4096 halves
    const size_t vBase = ((size_t)(b * 64 + tile)) << 14;   // *16384 halves
    const size_t qBase = ((size_t)(b * 32 + qt))   << 13;   // *8192 halves

    // V: fp16, [kg][c][slot]
    {
        const int vkg = j >> 4;
        const int vslot = sig(j & 15);
        const size_t vb2 = vBase + (size_t)vkg * 4096 + vslot;
#pragma unroll
        for (int i = 0; i < 32; i++) {
            float2 a = unpack2(accv[i]);
            int c0 = grp * 64 + 2 * i;
            g_v[vb2 + (size_t)c0 * 16]       = __float2half_rn(a.x + __ldg(&bv[c0]));
            g_v[vb2 + (size_t)(c0 + 1) * 16] = __float2half_rn(a.y + __ldg(&bv[c0 + 1]));
        }
    }
    // Q/K: fp16 hi/lo splits, [sec][row][slot]
#pragma unroll
    for (int i = 0; i < 4; i++) {
        float2 aq = unpack2(accq[i]);
        float2 ak = unpack2(acck[i]);
#pragma unroll
        for (int e2 = 0; e2 < 2; e2++) {
            const int d = grp * 8 + 2 * i + e2;
            const int kg = d >> 4;
            const int slot = sig(d & 15);
            // Q (log2e-scaled)
            float v = ((e2 ? aq.y : aq.x) + __ldg(&bq[d])) * LOG2E;
            __half h = __float2half_rn(v);
            __half lo = __float2half_rn(v - __half2float(h));
            g_q[qBase + (size_t)kg * 2048 + (size_t)qr * 16 + slot]        = h;
            g_q[qBase + (size_t)(2 + kg) * 2048 + (size_t)qr * 16 + slot]  = lo;
            // K
            v = (e2 ? ak.y : ak.x) + __ldg(&bk[d]);
            h = __float2half_rn(v);
            lo = __float2half_rn(v - __half2float(h));
            g_k[kBase + (size_t)kg * 1024 + (size_t)j * 16 + slot]         = h;
            g_k[kBase + (size_t)(2 + kg) * 1024 + (size_t)j * 16 + slot]   = lo;
        }
    }
}

// ====================================================================
// fp16 mma.sync flash attention, 512 thr / 16 warps (8 qw x 2 cg).
// cp.async.bulk 4-deep pipeline; online softmax per 32-key half-tile.
// SMEM: Q 16KB @0 ; buf[i] 40KB (K 8KB + V 32KB) @16KB+i*40KB ; mbars @180224.
// ====================================================================
#define SM_Q     0
#define SM_BUF   16384
#define BUF_SZ   40960
#define SM_MBAR  180224
#define ATTN_SMEM_BYTES 180352

__global__ void __launch_bounds__(512, 1) attn_mma(
    const float* __restrict__ x, float* __restrict__ out)
{
    extern __shared__ float sm[];
    const uint32_t sb = su32(sm);
    const int tid = threadIdx.x;
    const int w   = tid >> 5;
    const int qw  = w & 7;
    const int cg  = w >> 3;
    const int l   = tid & 31;
    const int l4  = l >> 2;
    const int t   = l & 3;
    const int b   = blockIdx.y;
    const int qt  = blockIdx.x;
    const int q0  = qt * TQ;

    const uint32_t mbQ = sb + SM_MBAR;
    const uint32_t mb0 = sb + SM_MBAR + 8;

    if (tid == 0) {
        MB_INIT(mbQ, 1);
#pragma unroll
        for (int i = 0; i < 4; i++) MB_INIT(mb0 + 8 * i, 1);
    }
    __syncthreads();

    if (tid == 0) {
        MB_EXPECT(mbQ, 16384);
        bulkcp(sb + SM_Q, (const char*)g_q + ((size_t)(b * 32 + qt) << 14), 16384, mbQ);
#pragma unroll
        for (int i = 0; i < 4; i++) {
            MB_EXPECT(mb0 + 8 * i, 40960);
            bulkcp(sb + SM_BUF + i * BUF_SZ,
                   (const char*)g_k + ((size_t)(b * 64 + i) << 13), 8192, mb0 + 8 * i);
            bulkcp(sb + SM_BUF + i * BUF_SZ + 8192,
                   (const char*)g_v + ((size_t)(b * 64 + i) << 15), 32768, mb0 + 8 * i);
        }
    }

    // ---- Q-hi fragments (register-resident) ----
    mb_wait(mbQ, 0);
    uint32_t qh[2][4];
    {
        const uint32_t rowb = sb + SM_Q + (uint32_t)(16 * qw + l4) * 32 + t * 8;
#pragma unroll
        for (int kg = 0; kg < 2; kg++) {
            lds64(qh[kg][0], qh[kg][2], rowb + kg * 4096);
            lds64(qh[kg][1], qh[kg][3], rowb + kg * 4096 + 256);
        }
    }
    const uint32_t qlob = sb + SM_Q + 8192 + (uint32_t)(16 * qw + l4) * 32 + t * 8;

    float o[16][4];
#pragma unroll
    for (int i = 0; i < 16; i++)
#pragma unroll
        for (int e = 0; e < 4; e++) o[i][e] = 0.f;
    float m0 = -1e30f, m1 = -1e30f, ls0 = 0.f, ls1 = 0.f;

    for (int tt = 0; tt < NT; tt++) {
        const int buf = tt & 3;
        const uint32_t kb = sb + SM_BUF + buf * BUF_SZ;
        const uint32_t vb = kb + 8192;
        mb_wait(mb0 + 8 * buf, (tt >> 2) & 1);

#pragma unroll
        for (int h = 0; h < 2; h++) {
            // ---- Q-lo fragments for this half (reloaded; kg-invariant) ----
            uint32_t ql[2][4];
#pragma unroll
            for (int kg = 0; kg < 2; kg++) {
                lds64(ql[kg][0], ql[kg][2], qlob + kg * 4096);
                lds64(ql[kg][1], ql[kg][3], qlob + kg * 4096 + 256);
            }
            // ---- S for 32 keys (4 n-tiles), fp16 hi/lo 3-pass ----
            float sacc[4][4];
#pragma unroll
            for (int nt = 0; nt < 4; nt++) {
#pragma unroll
                for (int e = 0; e < 4; e++) sacc[nt][e] = 0.f;
                const uint32_t ka = kb + (uint32_t)(((h * 4 + nt) * 8 + l4) * 32) + t * 8;
#pragma unroll
                for (int kg = 0; kg < 2; kg++) {
                    uint32_t bh0, bh1, bl0, bl1;
                    lds64(bh0, bh1, ka + kg * 2048);
                    lds64(bl0, bl1, ka + kg * 2048 + 4096);
                    mma_f16(sacc[nt], qh[kg][0], qh[kg][1], qh[kg][2], qh[kg][3], bh0, bh1);
                    mma_f16(sacc[nt], ql[kg][0], ql[kg][1], ql[kg][2], ql[kg][3], bh0, bh1);
                    mma_f16(sacc[nt], qh[kg][0], qh[kg][1], qh[kg][2], qh[kg][3], bl0, bl1);
                }
            }
            // ---- online max (quad-reduced) ----
            float mh0 = sacc[0][0], mh1 = sacc[0][2];
#pragma unroll
            for (int nt = 0; nt < 4; nt++) {
                mh0 = fmaxf(mh0, fmaxf(sacc[nt][0], sacc[nt][1]));
                mh1 = fmaxf(mh1, fmaxf(sacc[nt][2], sacc[nt][3]));
            }
            mh0 = fmaxf(mh0, __shfl_xor_sync(0xffffffffu, mh0, 1));
            mh0 = fmaxf(mh0, __shfl_xor_sync(0xffffffffu, mh0, 2));
            mh1 = fmaxf(mh1, __shfl_xor_sync(0xffffffffu, mh1, 1));
            mh1 = fmaxf(mh1, __shfl_xor_sync(0xffffffffu, mh1, 2));
            const float m0n = fmaxf(m0, mh0);
            const float m1n = fmaxf(m1, mh1);
            const float f0 = ex2f(m0 - m0n);
            const float f1 = ex2f(m1 - m1n);
            m0 = m0n; m1 = m1n;
            ls0 *= f0; ls1 *= f1;
#pragma unroll
            for (int i = 0; i < 16; i++) {
                o[i][0] *= f0; o[i][1] *= f0;
                o[i][2] *= f1; o[i][3] *= f1;
            }
            // ---- P (fp16) + PV per 16-key group ----
#pragma unroll
            for (int u = 0; u < 2; u++) {
                uint32_t A0, A1, A2, A3;
                {
                    float p0 = ex2f(sacc[2 * u][0] - m0), p1 = ex2f(sacc[2 * u][1] - m0);
                    float p2 = ex2f(sacc[2 * u][2] - m1), p3 = ex2f(sacc[2 * u][3] - m1);
                    A0 = packh2(p1, p0); A1 = packh2(p3, p2);
                    p0 = ex2f(sacc[2 * u + 1][0] - m0); p1 = ex2f(sacc[2 * u + 1][1] - m0);
                    p2 = ex2f(sacc[2 * u + 1][2] - m1); p3 = ex2f(sacc[2 * u + 1][3] - m1);
                    A2 = packh2(p1, p0); A3 = packh2(p3, p2);
                    ls0 += h2sum(A0) + h2sum(A2);
                    ls1 += h2sum(A1) + h2sum(A3);
                }
                uint32_t va = vb + (uint32_t)((h * 2 + u) * 8192)
                            + (uint32_t)((cg * 128 + l4) * 32) + t * 8;
#pragma unroll
                for (int nt2 = 0; nt2 < 16; nt2++) {
                    uint32_t b0, b1;
                    lds64(b0, b1, va);
                    mma_f16(o[nt2], A0, A1, A2, A3, b0, b1);
                    va += 256;   // next 8 channels (8 rows x 32B)
                }
            }
        }
        __syncthreads();   // all warps done with buf
        if (tid == 0 && tt + 4 < NT) {
            MB_EXPECT(mb0 + 8 * buf, 40960);
            bulkcp(kb, (const char*)g_k + ((size_t)(b * 64 + tt + 4) << 13), 8192, mb0 + 8 * buf);
            bulkcp(vb, (const char*)g_v + ((size_t)(b * 64 + tt + 4) << 15), 32768, mb0 + 8 * buf);
        }
    }

    // ---------------- epilogue ----------------
    ls0 += __shfl_xor_sync(0xffffffffu, ls0, 1);
    ls0 += __shfl_xor_sync(0xffffffffu, ls0, 2);
    ls1 += __shfl_xor_sync(0xffffffffu, ls1, 1);
    ls1 += __shfl_xor_sync(0xffffffffu, ls1, 2);
    const float inv0 = 1.0f / ls0;
    const float inv1 = 1.0f / ls1;

    float* stage = sm + (SM_BUF / 4);
    const int qlr = 16 * qw + l4;
#pragma unroll 1
    for (int ch = 0; ch < 4; ch++) {
        __syncthreads();
        if (cg == (ch >> 1)) {
#pragma unroll
            for (int k = 0; k < 8; k++) {
                const int nt2 = (ch & 1) * 8 + k;
                const int cloc = k * 8 + 2 * t;
                stage[cloc * 132 + qlr]           = o[nt2][0] * inv0;
                stage[(cloc + 1) * 132 + qlr]     = o[nt2][1] * inv0;
                stage[cloc * 132 + qlr + 8]       = o[nt2][2] * inv1;
                stage[(cloc + 1) * 132 + qlr + 8] = o[nt2][3] * inv1;
            }
        }
        __syncthreads();
        const int cloc2 = tid & 63;
        const int seg   = tid >> 6;
        const int cglob = ch * 64 + cloc2;
        const size_t gbase = ((size_t)(b * C_ + cglob)) * N_ + q0 + seg * 16;
        const float4* xs4 = (const float4*)(x + gbase);
        float4* os4 = (float4*)(out + gbase);
        const float* srow = stage + cloc2 * 132 + seg * 16;
#pragma unroll
        for (int i = 0; i < 4; i++) {
            float4 v = *(const float4*)(srow + 4 * i);
            float4 xv = xs4[i];
            float4 r;
            r.x = xv.x + v.x; r.y = xv.y + v.y; r.z = xv.z + v.z; r.w = xv.w + v.w;
            os4[i] = r;
        }
    }
}

// ====================================================================
extern "C" void kernel_launch(void* const* d_in, const int* in_sizes, int n_in,
                              void* d_out, int out_size)
{
    const float* x  = (const float*)d_in[0];
    const float* wq = (const float*)d_in[1];
    const float* bq = (const float*)d_in[2];
    const float* wk = (const float*)d_in[3];
    const float* bk = (const float*)d_in[4];
    const float* wv = (const float*)d_in[5];
    const float* bv = (const float*)d_in[6];
    float* out = (float*)d_out;

    cudaFuncSetAttribute(proj_kernel, cudaFuncAttributeMaxDynamicSharedMemorySize, PROJ_SMEM_BYTES);
    cudaFuncSetAttribute(attn_mma,    cudaFuncAttributeMaxDynamicSharedMemorySize, ATTN_SMEM_BYTES);

    proj_kernel<<<dim3(N_ / 64, B_), 256, PROJ_SMEM_BYTES>>>(x, wq, bq, wk, bk, wv, bv);
    attn_mma<<<dim3(N_ / TQ, B_), 512, ATTN_SMEM_BYTES>>>(x, out);
}

// round 9
// speedup vs baseline: 2.1484x; 1.2839x over previous
#include <cuda_runtime.h>
#include <cuda_fp16.h>
#include <cstdint>

#define B_  8
#define C_  256
#define N_  4096
#define CQ_ 32
#define TQ  128
#define TJ  64
#define NT  (N_ / TJ)

#define LOG2E 1.4426950408889634f

typedef unsigned long long ull;

// ---------------- gmem scratch: MMA-ready lds128 tile layouts ----------------
// g_q: [b][qtile 32] 16KB: [hi/lo 8KB][kg 4KB][qw 512B][lane 16B = row l4:(a0,a2) | row l4+8:(a1,a3)]
// g_k: [b][tile 64]   8KB: [hi/lo 4KB][knt 512B][lane 16B = kg0:(b0,b1) | kg1:(b0,b1)]
// g_v: [b][tile 64]  32KB: [u 8KB][pair 512B][lane 16B = grp2p:(b0,b1) | grp2p+1:(b0,b1)]
__device__ __align__(128) __half g_q[8 * 32 * 8192];
__device__ __align__(128) __half g_k[8 * 64 * 4096];
__device__ __align__(128) __half g_v[8 * 64 * 16384];

// ---------------- PTX helpers ----------------
__device__ __forceinline__ uint32_t su32(const void* p) {
    uint32_t a;
    asm("{ .reg .u64 t; cvta.to.shared.u64 t, %1; cvt.u32.u64 %0, t; }" : "=r"(a) : "l"(p));
    return a;
}
__device__ __forceinline__ float ex2f(float x) {
    float y;
    asm("ex2.approx.ftz.f32 %0, %1;" : "=f"(y) : "f"(x));
    return y;
}
__device__ __forceinline__ void lds128(uint32_t& a, uint32_t& b, uint32_t& c, uint32_t& d,
                                       uint32_t addr) {
    asm volatile("ld.shared.v4.b32 {%0, %1, %2, %3}, [%4];"
                 : "=r"(a), "=r"(b), "=r"(c), "=r"(d) : "r"(addr));
}
__device__ __forceinline__ void mma_f16(float* c, uint32_t a0, uint32_t a1,
                                        uint32_t a2, uint32_t a3,
                                        uint32_t b0, uint32_t b1) {
    asm volatile(
        "mma.sync.aligned.m16n8k16.row.col.f32.f16.f16.f32 "
        "{%0,%1,%2,%3}, {%4,%5,%6,%7}, {%8,%9}, {%0,%1,%2,%3};"
        : "+f"(c[0]), "+f"(c[1]), "+f"(c[2]), "+f"(c[3])
        : "r"(a0), "r"(a1), "r"(a2), "r"(a3), "r"(b0), "r"(b1));
}
__device__ __forceinline__ uint32_t packh2(float hi, float lo) {
    uint32_t u;
    asm("cvt.rn.f16x2.f32 %0, %1, %2;" : "=r"(u) : "f"(hi), "f"(lo));
    return u;
}
__device__ __forceinline__ float h2sum(uint32_t u) {
    float lo, hi;
    asm("{.reg .b16 l, h;\n mov.b32 {l, h}, %2;\n cvt.f32.f16 %0, l;\n cvt.f32.f16 %1, h;}"
        : "=f"(lo), "=f"(hi) : "r"(u));
    return lo + hi;
}
#define MB_INIT(mb, cnt) \
    asm volatile("mbarrier.init.shared.b64 [%0], %1;" :: "r"(mb), "r"(cnt) : "memory")
#define MB_EXPECT(mb, tx) \
    asm volatile("mbarrier.arrive.expect_tx.shared.b64 _, [%0], %1;" :: "r"(mb), "r"(tx) : "memory")
__device__ __forceinline__ void mb_wait(uint32_t mb, uint32_t parity) {
    asm volatile(
        "{\n .reg .pred P;\n"
        "W%=:\n"
        " mbarrier.try_wait.parity.acquire.cta.shared::cta.b64 P, [%0], %1, 0x989680;\n"
        " @P bra D%=;\n"
        " bra W%=;\n"
        "D%=:\n}"
        :: "r"(mb), "r"(parity) : "memory");
}
__device__ __forceinline__ void bulkcp(uint32_t dst, const void* src, uint32_t bytes, uint32_t mbar) {
    asm volatile(
        "cp.async.bulk.shared::cluster.global.mbarrier::complete_tx::bytes [%0], [%1], %2, [%3];"
        :: "r"(dst), "l"(src), "r"(bytes), "r"(mbar) : "memory");
}

// fragment slot: element e (0..15 within k16) -> slot (t = slot>>2, q = slot&3)
__device__ __forceinline__ int sig(int e) {
    return (e < 8) ? ((e >> 1) * 4 + (e & 1)) : (((e & 7) >> 1) * 4 + 2 + (e & 1));
}

// ---------------- packed f32x2 (proj compute) ----------------
__device__ __forceinline__ ull ffma2(ull a, ull b, ull c) {
    ull d; asm("fma.rn.f32x2 %0, %1, %2, %3;" : "=l"(d) : "l"(a), "l"(b), "l"(c)); return d;
}
__device__ __forceinline__ ull pack2(float x, float y) {
    ull r; asm("mov.b64 %0, {%1, %2};" : "=l"(r) : "f"(x), "f"(y)); return r;
}
__device__ __forceinline__ float2 unpack2(ull v) {
    float2 f; asm("mov.b64 {%0, %1}, %2;" : "=f"(f.x), "=f"(f.y) : "l"(v)); return f;
}

// ====================================================================
// Projection kernel: math unchanged; stores write the lds128 layouts.
// ====================================================================
#define PROJ_SMEM_FLOATS (2048 + 32*258 + 32*36 + 32*36)
#define PROJ_SMEM_BYTES  (PROJ_SMEM_FLOATS * 4)

__global__ void __launch_bounds__(256) proj_kernel(
    const float* __restrict__ x,
    const float* __restrict__ wq, const float* __restrict__ bq,
    const float* __restrict__ wk, const float* __restrict__ bk,
    const float* __restrict__ wv, const float* __restrict__ bv)
{
    extern __shared__ float sm[];
    float* xs  = sm;
    float* wvs = sm + 2048;
    float* wqs = wvs + 32 * 258;
    float* wks = wqs + 32 * 36;

    const int tid = threadIdx.x;
    const int n   = tid & 63;
    const int grp = tid >> 6;
    const int b   = blockIdx.y;
    const int n0  = blockIdx.x * 64;

    ull accv[32]; ull accq[4], acck[4];
#pragma unroll
    for (int i = 0; i < 32; i++) accv[i] = 0ull;
#pragma unroll
    for (int i = 0; i < 4; i++) { accq[i] = 0ull; acck[i] = 0ull; }

    for (int kc = 0; kc < 8; kc++) {
        __syncthreads();
        {
            const float4* xg = (const float4*)(x + ((size_t)b * C_ + kc * 32) * N_ + n0);
            float4* xs4 = (float4*)xs;
            for (int i = tid; i < 32 * 16; i += 256) {
                int ci = i >> 4, n4 = i & 15;
                xs4[ci * 16 + n4] = xg[(size_t)ci * (N_ / 4) + n4];
            }
        }
        for (int i = tid; i < 256 * 32; i += 256) {
            int co = i >> 5, ci = i & 31;
            wvs[ci * 258 + co] = wv[co * C_ + kc * 32 + ci];
        }
        for (int i = tid; i < 32 * 32; i += 256) {
            int d = i >> 5, ci = i & 31;
            wqs[ci * 36 + d] = wq[d * C_ + kc * 32 + ci];
            wks[ci * 36 + d] = wk[d * C_ + kc * 32 + ci];
        }
        __syncthreads();

#pragma unroll 4
        for (int ci = 0; ci < 32; ci++) {
            float xv = xs[ci * 64 + n];
            ull  xv2 = pack2(xv, xv);
            const ull* wr  = (const ull*)&wvs[ci * 258 + grp * 64];
#pragma unroll
            for (int i = 0; i < 32; i++) accv[i] = ffma2(wr[i], xv2, accv[i]);
            const ull* wrq = (const ull*)&wqs[ci * 36 + grp * 8];
            const ull* wrk = (const ull*)&wks[ci * 36 + grp * 8];
#pragma unroll
            for (int i = 0; i < 4; i++) {
                accq[i] = ffma2(wrq[i], xv2, accq[i]);
                acck[i] = ffma2(wrk[i], xv2, acck[i]);
            }
        }
    }

    const int np   = n0 + n;
    const int tile = np >> 6;
    const int j    = np & 63;       // key within tile
    const int qt   = np >> 7;
    const int r    = np & 127;      // query row within qtile
    const size_t kBase = ((size_t)(b * 64 + tile)) << 12;
    const size_t vBase = ((size_t)(b * 64 + tile)) << 14;
    const size_t qBase = ((size_t)(b * 32 + qt))   << 13;

    // ---- V: [u][pair][lane][s][q] ----
    {
        const int u  = j >> 4;
        const int sl = sig(j & 15);
        const int tV = sl >> 2, qV = sl & 3;
        const size_t vb2 = vBase + (size_t)u * 4096 + tV * 8 + qV;
#pragma unroll
        for (int i = 0; i < 32; i++) {
            float2 a = unpack2(accv[i]);
            int c0 = grp * 64 + 2 * i;
            size_t o0 = vb2 + (size_t)(c0 >> 4) * 256 + (size_t)(c0 & 7) * 32
                      + (size_t)((c0 >> 3) & 1) * 4;
            int c1 = c0 + 1;
            size_t o1 = vb2 + (size_t)(c1 >> 4) * 256 + (size_t)(c1 & 7) * 32
                      + (size_t)((c1 >> 3) & 1) * 4;
            g_v[o0] = __float2half_rn(a.x + __ldg(&bv[c0]));
            g_v[o1] = __float2half_rn(a.y + __ldg(&bv[c1]));
        }
    }
    // ---- Q/K hi/lo ----
    {
        const int knt = j >> 3, l4k = j & 7;
        const int qw = r >> 4, rr = r & 15;
        const int l4q = rr & 7, rowsel = rr >> 3;
#pragma unroll
        for (int i = 0; i < 4; i++) {
            float2 aq = unpack2(accq[i]);
            float2 ak = unpack2(acck[i]);
#pragma unroll
            for (int e2 = 0; e2 < 2; e2++) {
                const int d  = grp * 8 + 2 * i + e2;
                const int kg = d >> 4;
                const int sl = sig(d & 15);
                const int tt = sl >> 2, qq = sl & 3;
                // Q (log2e-scaled)
                float v = ((e2 ? aq.y : aq.x) + __ldg(&bq[d])) * LOG2E;
                __half h  = __float2half_rn(v);
                __half lo = __float2half_rn(v - __half2float(h));
                size_t qo = qBase + (size_t)kg * 2048 + (size_t)qw * 256
                          + (size_t)(l4q * 4 + tt) * 8 + rowsel * 4 + qq;
                g_q[qo]        = h;
                g_q[qo + 4096] = lo;
                // K  (FIX: knt unit is 256 halves = 512 bytes, was 128)
                v  = (e2 ? ak.y : ak.x) + __ldg(&bk[d]);
                h  = __float2half_rn(v);
                lo = __float2half_rn(v - __half2float(h));
                size_t ko = kBase + (size_t)knt * 256
                          + (size_t)(l4k * 4 + tt) * 8 + kg * 4 + qq;
                g_k[ko]        = h;
                g_k[ko + 2048] = lo;
            }
        }
    }
}

// ====================================================================
// fp16 flash attention, 512 thr / 16 warps (8 qw x 2 cg), lds128 frags.
// ====================================================================
#define SM_Q     0
#define SM_BUF   16384
#define BUF_SZ   40960
#define SM_MBAR  180224
#define ATTN_SMEM_BYTES 180352

__global__ void __launch_bounds__(512, 1) attn_mma(
    const float* __restrict__ x, float* __restrict__ out)
{
    extern __shared__ float sm[];
    const uint32_t sb = su32(sm);
    const int tid = threadIdx.x;
    const int w   = tid >> 5;
    const int qw  = w & 7;
    const int cg  = w >> 3;
    const int l   = tid & 31;
    const int l4  = l >> 2;
    const int t   = l & 3;
    const int b   = blockIdx.y;
    const int qt  = blockIdx.x;
    const int q0  = qt * TQ;
    const uint32_t lane16 = (uint32_t)l * 16;

    const uint32_t mbQ = sb + SM_MBAR;
    const uint32_t mb0 = sb + SM_MBAR + 8;

    if (tid == 0) {
        MB_INIT(mbQ, 1);
#pragma unroll
        for (int i = 0; i < 4; i++) MB_INIT(mb0 + 8 * i, 1);
    }
    __syncthreads();

    if (tid == 0) {
        MB_EXPECT(mbQ, 16384);
        bulkcp(sb + SM_Q, (const char*)g_q + ((size_t)(b * 32 + qt) << 14), 16384, mbQ);
#pragma unroll
        for (int i = 0; i < 4; i++) {
            MB_EXPECT(mb0 + 8 * i, 40960);
            bulkcp(sb + SM_BUF + i * BUF_SZ,
                   (const char*)g_k + ((size_t)(b * 64 + i) << 13), 8192, mb0 + 8 * i);
            bulkcp(sb + SM_BUF + i * BUF_SZ + 8192,
                   (const char*)g_v + ((size_t)(b * 64 + i) << 15), 32768, mb0 + 8 * i);
        }
    }

    // ---- Q-hi fragments (register-resident): 1 lds128 per kg ----
    mb_wait(mbQ, 0);
    uint32_t qh[2][4];
#pragma unroll
    for (int kg = 0; kg < 2; kg++) {
        uint32_t x0, x1, x2, x3;
        lds128(x0, x1, x2, x3, sb + SM_Q + kg * 4096 + qw * 512 + lane16);
        qh[kg][0] = x0; qh[kg][1] = x2; qh[kg][2] = x1; qh[kg][3] = x3;
    }
    const uint32_t qlob = sb + SM_Q + 8192 + qw * 512 + lane16;

    float o[16][4];
#pragma unroll
    for (int i = 0; i < 16; i++)
#pragma unroll
        for (int e = 0; e < 4; e++) o[i][e] = 0.f;
    float m0 = -1e30f, m1 = -1e30f, ls0 = 0.f, ls1 = 0.f;

    for (int tt = 0; tt < NT; tt++) {
        const int buf = tt & 3;
        const uint32_t kb = sb + SM_BUF + buf * BUF_SZ;
        const uint32_t vb = kb + 8192;
        mb_wait(mb0 + 8 * buf, (tt >> 2) & 1);

#pragma unroll
        for (int h = 0; h < 2; h++) {
            // ---- Q-lo fragments (reloaded; 2 lds128) ----
            uint32_t ql[2][4];
#pragma unroll
            for (int kg = 0; kg < 2; kg++) {
                uint32_t x0, x1, x2, x3;
                lds128(x0, x1, x2, x3, qlob + kg * 4096);
                ql[kg][0] = x0; ql[kg][1] = x2; ql[kg][2] = x1; ql[kg][3] = x3;
            }
            // ---- S for 32 keys (4 n-tiles), hi/lo 3-pass, 2 lds128/nt ----
            // FIX: knt unit stride is 512 bytes (was 256)
            float sacc[4][4];
#pragma unroll
            for (int nt = 0; nt < 4; nt++) {
#pragma unroll
                for (int e = 0; e < 4; e++) sacc[nt][e] = 0.f;
                const uint32_t ka = kb + (uint32_t)((h * 4 + nt) * 512) + lane16;
                uint32_t h0, h1, h2, h3, g0, g1, g2, g3;
                lds128(h0, h1, h2, h3, ka);
                lds128(g0, g1, g2, g3, ka + 4096);
                mma_f16(sacc[nt], qh[0][0], qh[0][1], qh[0][2], qh[0][3], h0, h1);
                mma_f16(sacc[nt], qh[1][0], qh[1][1], qh[1][2], qh[1][3], h2, h3);
                mma_f16(sacc[nt], ql[0][0], ql[0][1], ql[0][2], ql[0][3], h0, h1);
                mma_f16(sacc[nt], ql[1][0], ql[1][1], ql[1][2], ql[1][3], h2, h3);
                mma_f16(sacc[nt], qh[0][0], qh[0][1], qh[0][2], qh[0][3], g0, g1);
                mma_f16(sacc[nt], qh[1][0], qh[1][1], qh[1][2], qh[1][3], g2, g3);
            }
            // ---- online max (quad-reduced) ----
            float mh0 = sacc[0][0], mh1 = sacc[0][2];
#pragma unroll
            for (int nt = 0; nt < 4; nt++) {
                mh0 = fmaxf(mh0, fmaxf(sacc[nt][0], sacc[nt][1]));
                mh1 = fmaxf(mh1, fmaxf(sacc[nt][2], sacc[nt][3]));
            }
            mh0 = fmaxf(mh0, __shfl_xor_sync(0xffffffffu, mh0, 1));
            mh0 = fmaxf(mh0, __shfl_xor_sync(0xffffffffu, mh0, 2));
            mh1 = fmaxf(mh1, __shfl_xor_sync(0xffffffffu, mh1, 1));
            mh1 = fmaxf(mh1, __shfl_xor_sync(0xffffffffu, mh1, 2));
            const float m0n = fmaxf(m0, mh0);
            const float m1n = fmaxf(m1, mh1);
            bool chg = (m0n > m0) || (m1n > m1);
            if (__any_sync(0xffffffffu, chg)) {
                const float f0 = ex2f(m0 - m0n);
                const float f1 = ex2f(m1 - m1n);
                m0 = m0n; m1 = m1n;
                ls0 *= f0; ls1 *= f1;
#pragma unroll
                for (int i = 0; i < 16; i++) {
                    o[i][0] *= f0; o[i][1] *= f0;
                    o[i][2] *= f1; o[i][3] *= f1;
                }
            }
            // ---- P (fp16) + PV per 16-key group, 8 lds128 each ----
#pragma unroll
            for (int u = 0; u < 2; u++) {
                uint32_t A0, A1, A2, A3;
                {
                    float p0 = ex2f(sacc[2 * u][0] - m0), p1 = ex2f(sacc[2 * u][1] - m0);
                    float p2 = ex2f(sacc[2 * u][2] - m1), p3 = ex2f(sacc[2 * u][3] - m1);
                    A0 = packh2(p1, p0); A1 = packh2(p3, p2);
                    p0 = ex2f(sacc[2 * u + 1][0] - m0); p1 = ex2f(sacc[2 * u + 1][1] - m0);
                    p2 = ex2f(sacc[2 * u + 1][2] - m1); p3 = ex2f(sacc[2 * u + 1][3] - m1);
                    A2 = packh2(p1, p0); A3 = packh2(p3, p2);
                    ls0 += h2sum(A0) + h2sum(A2);
                    ls1 += h2sum(A1) + h2sum(A3);
                }
                uint32_t va = vb + (uint32_t)((h * 2 + u) * 8192) + (uint32_t)(cg * 4096) + lane16;
#pragma unroll
                for (int p = 0; p < 8; p++) {
                    uint32_t v0, v1, v2, v3;
                    lds128(v0, v1, v2, v3, va);
                    mma_f16(o[2 * p],     A0, A1, A2, A3, v0, v1);
                    mma_f16(o[2 * p + 1], A0, A1, A2, A3, v2, v3);
                    va += 512;
                }
            }
        }
        __syncthreads();
        if (tid == 0 && tt + 4 < NT) {
            MB_EXPECT(mb0 + 8 * buf, 40960);
            bulkcp(kb, (const char*)g_k + ((size_t)(b * 64 + tt + 4) << 13), 8192, mb0 + 8 * buf);
            bulkcp(vb, (const char*)g_v + ((size_t)(b * 64 + tt + 4) << 15), 32768, mb0 + 8 * buf);
        }
    }

    // ---------------- epilogue ----------------
    ls0 += __shfl_xor_sync(0xffffffffu, ls0, 1);
    ls0 += __shfl_xor_sync(0xffffffffu, ls0, 2);
    ls1 += __shfl_xor_sync(0xffffffffu, ls1, 1);
    ls1 += __shfl_xor_sync(0xffffffffu, ls1, 2);
    const float inv0 = 1.0f / ls0;
    const float inv1 = 1.0f / ls1;

    float* stage = sm + (SM_BUF / 4);
    const int qlr = 16 * qw + l4;
#pragma unroll 1
    for (int ch = 0; ch < 4; ch++) {
        __syncthreads();
        if (cg == (ch >> 1)) {
#pragma unroll
            for (int k = 0; k < 8; k++) {
                const int nt2 = (ch & 1) * 8 + k;
                const int cloc = k * 8 + 2 * t;
                stage[cloc * 132 + qlr]           = o[nt2][0] * inv0;
                stage[(cloc + 1) * 132 + qlr]     = o[nt2][1] * inv0;
                stage[cloc * 132 + qlr + 8]       = o[nt2][2] * inv1;
                stage[(cloc + 1) * 132 + qlr + 8] = o[nt2][3] * inv1;
            }
        }
        __syncthreads();
        const int cloc2 = tid & 63;
        const int seg   = tid >> 6;
        const int cglob = ch * 64 + cloc2;
        const size_t gbase = ((size_t)(b * C_ + cglob)) * N_ + q0 + seg * 16;
        const float4* xs4 = (const float4*)(x + gbase);
        float4* os4 = (float4*)(out + gbase);
        const float* srow = stage + cloc2 * 132 + seg * 16;
#pragma unroll
        for (int i = 0; i < 4; i++) {
            float4 v = *(const float4*)(srow + 4 * i);
            float4 xv = xs4[i];
            float4 r;
            r.x = xv.x + v.x; r.y = xv.y + v.y; r.z = xv.z + v.z; r.w = xv.w + v.w;
            os4[i] = r;
        }
    }
}

// ====================================================================
extern "C" void kernel_launch(void* const* d_in, const int* in_sizes, int n_in,
                              void* d_out, int out_size)
{
    const float* x  = (const float*)d_in[0];
    const float* wq = (const float*)d_in[1];
    const float* bq = (const float*)d_in[2];
    const float* wk = (const float*)d_in[3];
    const float* bk = (const float*)d_in[4];
    const float* wv = (const float*)d_in[5];
    const float* bv = (const float*)d_in[6];
    float* out = (float*)d_out;

    cudaFuncSetAttribute(proj_kernel, cudaFuncAttributeMaxDynamicSharedMemorySize, PROJ_SMEM_BYTES);
    cudaFuncSetAttribute(attn_mma,    cudaFuncAttributeMaxDynamicSharedMemorySize, ATTN_SMEM_BYTES);

    proj_kernel<<<dim3(N_ / 64, B_), 256, PROJ_SMEM_BYTES>>>(x, wq, bq, wk, bk, wv, bv);
    attn_mma<<<dim3(N_ / TQ, B_), 512, ATTN_SMEM_BYTES>>>(x, out);
}

// round 10
// speedup vs baseline: 2.4504x; 1.1406x over previous
#include <cuda_runtime.h>
#include <cuda_fp16.h>
#include <cstdint>

#define B_  8
#define C_  256
#define N_  4096
#define CQ_ 32
#define TQ  128
#define TJ  64
#define NT  (N_ / TJ)

#define LOG2E 1.4426950408889634f

typedef unsigned long long ull;

// ---------------- gmem scratch: MMA-ready lds128 tile layouts ----------------
__device__ __align__(128) __half g_q[8 * 32 * 8192];
__device__ __align__(128) __half g_k[8 * 64 * 4096];
__device__ __align__(128) __half g_v[8 * 64 * 16384];

// ---------------- PTX helpers ----------------
__device__ __forceinline__ uint32_t su32(const void* p) {
    uint32_t a;
    asm("{ .reg .u64 t; cvta.to.shared.u64 t, %1; cvt.u32.u64 %0, t; }" : "=r"(a) : "l"(p));
    return a;
}
__device__ __forceinline__ float ex2f(float x) {
    float y;
    asm("ex2.approx.ftz.f32 %0, %1;" : "=f"(y) : "f"(x));
    return y;
}
__device__ __forceinline__ void lds128(uint32_t& a, uint32_t& b, uint32_t& c, uint32_t& d,
                                       uint32_t addr) {
    asm volatile("ld.shared.v4.b32 {%0, %1, %2, %3}, [%4];"
                 : "=r"(a), "=r"(b), "=r"(c), "=r"(d) : "r"(addr));
}
__device__ __forceinline__ void sts128(uint32_t addr, uint32_t a, uint32_t b,
                                       uint32_t c, uint32_t d) {
    asm volatile("st.shared.v4.b32 [%0], {%1, %2, %3, %4};"
                 :: "r"(addr), "r"(a), "r"(b), "r"(c), "r"(d) : "memory");
}
__device__ __forceinline__ void sts_f2(uint32_t addr, float a, float b) {
    asm volatile("st.shared.v2.f32 [%0], {%1, %2};" :: "r"(addr), "f"(a), "f"(b) : "memory");
}
__device__ __forceinline__ void lds_f2(float& a, float& b, uint32_t addr) {
    asm volatile("ld.shared.v2.f32 {%0, %1}, [%2];" : "=f"(a), "=f"(b) : "r"(addr));
}
__device__ __forceinline__ void mma_f16(float* c, uint32_t a0, uint32_t a1,
                                        uint32_t a2, uint32_t a3,
                                        uint32_t b0, uint32_t b1) {
    asm volatile(
        "mma.sync.aligned.m16n8k16.row.col.f32.f16.f16.f32 "
        "{%0,%1,%2,%3}, {%4,%5,%6,%7}, {%8,%9}, {%0,%1,%2,%3};"
        : "+f"(c[0]), "+f"(c[1]), "+f"(c[2]), "+f"(c[3])
        : "r"(a0), "r"(a1), "r"(a2), "r"(a3), "r"(b0), "r"(b1));
}
__device__ __forceinline__ uint32_t packh2(float hi, float lo) {
    uint32_t u;
    asm("cvt.rn.f16x2.f32 %0, %1, %2;" : "=r"(u) : "f"(hi), "f"(lo));
    return u;
}
__device__ __forceinline__ float h2sum(uint32_t u) {
    float lo, hi;
    asm("{.reg .b16 l, h;\n mov.b32 {l, h}, %2;\n cvt.f32.f16 %0, l;\n cvt.f32.f16 %1, h;}"
        : "=f"(lo), "=f"(hi) : "r"(u));
    return lo + hi;
}
#define MB_INIT(mb, cnt) \
    asm volatile("mbarrier.init.shared.b64 [%0], %1;" :: "r"(mb), "r"(cnt) : "memory")
#define MB_EXPECT(mb, tx) \
    asm volatile("mbarrier.arrive.expect_tx.shared.b64 _, [%0], %1;" :: "r"(mb), "r"(tx) : "memory")
#define MB_ARRIVE(mb) \
    asm volatile("mbarrier.arrive.shared.b64 _, [%0];" :: "r"(mb) : "memory")
__device__ __forceinline__ void mb_wait(uint32_t mb, uint32_t parity) {
    asm volatile(
        "{\n .reg .pred P;\n"
        "W%=:\n"
        " mbarrier.try_wait.parity.acquire.cta.shared::cta.b64 P, [%0], %1, 0x989680;\n"
        " @P bra D%=;\n"
        " bra W%=;\n"
        "D%=:\n}"
        :: "r"(mb), "r"(parity) : "memory");
}
__device__ __forceinline__ void bulkcp(uint32_t dst, const void* src, uint32_t bytes, uint32_t mbar) {
    asm volatile(
        "cp.async.bulk.shared::cluster.global.mbarrier::complete_tx::bytes [%0], [%1], %2, [%3];"
        :: "r"(dst), "l"(src), "r"(bytes), "r"(mbar) : "memory");
}
#define BAR_PAIR(id) \
    asm volatile("bar.sync %0, 64;" :: "r"(id) : "memory")

// fragment slot: element e (0..15 within k16) -> slot (t = slot>>2, q = slot&3)
__device__ __forceinline__ int sig(int e) {
    return (e < 8) ? ((e >> 1) * 4 + (e & 1)) : (((e & 7) >> 1) * 4 + 2 + (e & 1));
}

// ---------------- packed f32x2 (proj compute) ----------------
__device__ __forceinline__ ull ffma2(ull a, ull b, ull c) {
    ull d; asm("fma.rn.f32x2 %0, %1, %2, %3;" : "=l"(d) : "l"(a), "l"(b), "l"(c)); return d;
}
__device__ __forceinline__ ull pack2(float x, float y) {
    ull r; asm("mov.b64 %0, {%1, %2};" : "=l"(r) : "f"(x), "f"(y)); return r;
}
__device__ __forceinline__ float2 unpack2(ull v) {
    float2 f; asm("mov.b64 {%0, %1}, %2;" : "=f"(f.x), "=f"(f.y) : "l"(v)); return f;
}

// ====================================================================
// Projection kernel (unchanged from round 9).
// ====================================================================
#define PROJ_SMEM_FLOATS (2048 + 32*258 + 32*36 + 32*36)
#define PROJ_SMEM_BYTES  (PROJ_SMEM_FLOATS * 4)

__global__ void __launch_bounds__(256) proj_kernel(
    const float* __restrict__ x,
    const float* __restrict__ wq, const float* __restrict__ bq,
    const float* __restrict__ wk, const float* __restrict__ bk,
    const float* __restrict__ wv, const float* __restrict__ bv)
{
    extern __shared__ float sm[];
    float* xs  = sm;
    float* wvs = sm + 2048;
    float* wqs = wvs + 32 * 258;
    float* wks = wqs + 32 * 36;

    const int tid = threadIdx.x;
    const int n   = tid & 63;
    const int grp = tid >> 6;
    const int b   = blockIdx.y;
    const int n0  = blockIdx.x * 64;

    ull accv[32]; ull accq[4], acck[4];
#pragma unroll
    for (int i = 0; i < 32; i++) accv[i] = 0ull;
#pragma unroll
    for (int i = 0; i < 4; i++) { accq[i] = 0ull; acck[i] = 0ull; }

    for (int kc = 0; kc < 8; kc++) {
        __syncthreads();
        {
            const float4* xg = (const float4*)(x + ((size_t)b * C_ + kc * 32) * N_ + n0);
            float4* xs4 = (float4*)xs;
            for (int i = tid; i < 32 * 16; i += 256) {
                int ci = i >> 4, n4 = i & 15;
                xs4[ci * 16 + n4] = xg[(size_t)ci * (N_ / 4) + n4];
            }
        }
        for (int i = tid; i < 256 * 32; i += 256) {
            int co = i >> 5, ci = i & 31;
            wvs[ci * 258 + co] = wv[co * C_ + kc * 32 + ci];
        }
        for (int i = tid; i < 32 * 32; i += 256) {
            int d = i >> 5, ci = i & 31;
            wqs[ci * 36 + d] = wq[d * C_ + kc * 32 + ci];
            wks[ci * 36 + d] = wk[d * C_ + kc * 32 + ci];
        }
        __syncthreads();

#pragma unroll 4
        for (int ci = 0; ci < 32; ci++) {
            float xv = xs[ci * 64 + n];
            ull  xv2 = pack2(xv, xv);
            const ull* wr  = (const ull*)&wvs[ci * 258 + grp * 64];
#pragma unroll
            for (int i = 0; i < 32; i++) accv[i] = ffma2(wr[i], xv2, accv[i]);
            const ull* wrq = (const ull*)&wqs[ci * 36 + grp * 8];
            const ull* wrk = (const ull*)&wks[ci * 36 + grp * 8];
#pragma unroll
            for (int i = 0; i < 4; i++) {
                accq[i] = ffma2(wrq[i], xv2, accq[i]);
                acck[i] = ffma2(wrk[i], xv2, acck[i]);
            }
        }
    }

    const int np   = n0 + n;
    const int tile = np >> 6;
    const int j    = np & 63;
    const int qt   = np >> 7;
    const int r    = np & 127;
    const size_t kBase = ((size_t)(b * 64 + tile)) << 12;
    const size_t vBase = ((size_t)(b * 64 + tile)) << 14;
    const size_t qBase = ((size_t)(b * 32 + qt))   << 13;

    {
        const int u  = j >> 4;
        const int sl = sig(j & 15);
        const int tV = sl >> 2, qV = sl & 3;
        const size_t vb2 = vBase + (size_t)u * 4096 + tV * 8 + qV;
#pragma unroll
        for (int i = 0; i < 32; i++) {
            float2 a = unpack2(accv[i]);
            int c0 = grp * 64 + 2 * i;
            size_t o0 = vb2 + (size_t)(c0 >> 4) * 256 + (size_t)(c0 & 7) * 32
                      + (size_t)((c0 >> 3) & 1) * 4;
            int c1 = c0 + 1;
            size_t o1 = vb2 + (size_t)(c1 >> 4) * 256 + (size_t)(c1 & 7) * 32
                      + (size_t)((c1 >> 3) & 1) * 4;
            g_v[o0] = __float2half_rn(a.x + __ldg(&bv[c0]));
            g_v[o1] = __float2half_rn(a.y + __ldg(&bv[c1]));
        }
    }
    {
        const int knt = j >> 3, l4k = j & 7;
        const int qw = r >> 4, rr = r & 15;
        const int l4q = rr & 7, rowsel = rr >> 3;
#pragma unroll
        for (int i = 0; i < 4; i++) {
            float2 aq = unpack2(accq[i]);
            float2 ak = unpack2(acck[i]);
#pragma unroll
            for (int e2 = 0; e2 < 2; e2++) {
                const int d  = grp * 8 + 2 * i + e2;
                const int kg = d >> 4;
                const int sl = sig(d & 15);
                const int tt = sl >> 2, qq = sl & 3;
                float v = ((e2 ? aq.y : aq.x) + __ldg(&bq[d])) * LOG2E;
                __half h  = __float2half_rn(v);
                __half lo = __float2half_rn(v - __half2float(h));
                size_t qo = qBase + (size_t)kg * 2048 + (size_t)qw * 256
                          + (size_t)(l4q * 4 + tt) * 8 + rowsel * 4 + qq;
                g_q[qo]        = h;
                g_q[qo + 4096] = lo;
                v  = (e2 ? ak.y : ak.x) + __ldg(&bk[d]);
                h  = __float2half_rn(v);
                lo = __float2half_rn(v - __half2float(h));
                size_t ko = kBase + (size_t)knt * 256
                          + (size_t)(l4k * 4 + tt) * 8 + kg * 4 + qq;
                g_k[ko]        = h;
                g_k[ko + 2048] = lo;
            }
        }
    }
}

// ====================================================================
// fp16 flash attention: S split between cg pair + P-sharing via SMEM;
// buffer recycling via consumed-mbarrier (no per-tile CTA barrier).
// ====================================================================
#define SM_Q     0
#define SM_BUF   16384
#define BUF_SZ   40960
#define SM_MBAR  180224     /* mbQ@+0, data@+8..40, cons@+40..72 */
#define SM_PSH   180352     /* P fragments: [qw 8][u 4][lane 16B] = 16KB */
#define SM_MX    196736     /* tile-half maxes: [qw][cg][l4] x 8B = 1KB  */
#define SM_LS    197760     /* final ls: [qw][cg][l4] x 8B = 1KB        */
#define ATTN_SMEM_BYTES 198784

__global__ void __launch_bounds__(512, 1) attn_mma(
    const float* __restrict__ x, float* __restrict__ out)
{
    extern __shared__ float sm[];
    const uint32_t sb = su32(sm);
    const int tid = threadIdx.x;
    const int w   = tid >> 5;
    const int qw  = w & 7;
    const int cg  = w >> 3;
    const int l   = tid & 31;
    const int l4  = l >> 2;
    const int t   = l & 3;
    const int b   = blockIdx.y;
    const int qt  = blockIdx.x;
    const int q0  = qt * TQ;
    const uint32_t lane16 = (uint32_t)l * 16;
    const int barid = 1 + qw;

    const uint32_t mbQ  = sb + SM_MBAR;
    const uint32_t mbD  = sb + SM_MBAR + 8;
    const uint32_t mbC  = sb + SM_MBAR + 40;
    const uint32_t mxO  = sb + SM_MX + (uint32_t)(((qw * 2 + cg) * 8 + l4) * 8);
    const uint32_t mxP  = sb + SM_MX + (uint32_t)(((qw * 2 + (1 - cg)) * 8 + l4) * 8);
    const uint32_t pshQ = sb + SM_PSH + (uint32_t)(qw * 2048) + lane16;

    if (tid == 0) {
        MB_INIT(mbQ, 1);
#pragma unroll
        for (int i = 0; i < 4; i++) { MB_INIT(mbD + 8 * i, 1); MB_INIT(mbC + 8 * i, 16); }
    }
    __syncthreads();

    if (tid == 0) {
        MB_EXPECT(mbQ, 16384);
        bulkcp(sb + SM_Q, (const char*)g_q + ((size_t)(b * 32 + qt) << 14), 16384, mbQ);
#pragma unroll
        for (int i = 0; i < 4; i++) {
            MB_EXPECT(mbD + 8 * i, 40960);
            bulkcp(sb + SM_BUF + i * BUF_SZ,
                   (const char*)g_k + ((size_t)(b * 64 + i) << 13), 8192, mbD + 8 * i);
            bulkcp(sb + SM_BUF + i * BUF_SZ + 8192,
                   (const char*)g_v + ((size_t)(b * 64 + i) << 15), 32768, mbD + 8 * i);
        }
    }

    // ---- Q-hi fragments (register-resident) ----
    mb_wait(mbQ, 0);
    uint32_t qh[2][4];
#pragma unroll
    for (int kg = 0; kg < 2; kg++) {
        uint32_t x0, x1, x2, x3;
        lds128(x0, x1, x2, x3, sb + SM_Q + kg * 4096 + qw * 512 + lane16);
        qh[kg][0] = x0; qh[kg][1] = x2; qh[kg][2] = x1; qh[kg][3] = x3;
    }
    const uint32_t qlob = sb + SM_Q + 8192 + qw * 512 + lane16;

    float o[16][4];
#pragma unroll
    for (int i = 0; i < 16; i++)
#pragma unroll
        for (int e = 0; e < 4; e++) o[i][e] = 0.f;
    float m0 = -1e30f, m1 = -1e30f, ls0 = 0.f, ls1 = 0.f;

    for (int tt = 0; tt < NT; tt++) {
        const int buf = tt & 3;
        const uint32_t kb = sb + SM_BUF + (uint32_t)buf * BUF_SZ;
        const uint32_t vb = kb + 8192;
        const uint32_t par = (uint32_t)((tt >> 2) & 1);
        mb_wait(mbD + 8 * buf, par);

        // ---- Q-lo fragments (own half only; 2 lds128) ----
        uint32_t ql[2][4];
#pragma unroll
        for (int kg = 0; kg < 2; kg++) {
            uint32_t x0, x1, x2, x3;
            lds128(x0, x1, x2, x3, qlob + kg * 4096);
            ql[kg][0] = x0; ql[kg][1] = x2; ql[kg][2] = x1; ql[kg][3] = x3;
        }
        // ---- S for OWN 32-key half (4 n-tiles, hi/lo 3-pass) ----
        float sacc[4][4];
        const uint32_t kaBase = kb + (uint32_t)(cg * 2048) + lane16;
#pragma unroll
        for (int nt = 0; nt < 4; nt++) {
#pragma unroll
            for (int e = 0; e < 4; e++) sacc[nt][e] = 0.f;
            const uint32_t ka = kaBase + (uint32_t)(nt * 512);
            uint32_t h0, h1, h2, h3, g0, g1, g2, g3;
            lds128(h0, h1, h2, h3, ka);
            lds128(g0, g1, g2, g3, ka + 4096);
            mma_f16(sacc[nt], qh[0][0], qh[0][1], qh[0][2], qh[0][3], h0, h1);
            mma_f16(sacc[nt], qh[1][0], qh[1][1], qh[1][2], qh[1][3], h2, h3);
            mma_f16(sacc[nt], ql[0][0], ql[0][1], ql[0][2], ql[0][3], h0, h1);
            mma_f16(sacc[nt], ql[1][0], ql[1][1], ql[1][2], ql[1][3], h2, h3);
            mma_f16(sacc[nt], qh[0][0], qh[0][1], qh[0][2], qh[0][3], g0, g1);
            mma_f16(sacc[nt], qh[1][0], qh[1][1], qh[1][2], qh[1][3], g2, g3);
        }
        // ---- own-half max (quad-reduced), exchange with partner ----
        float mh0 = sacc[0][0], mh1 = sacc[0][2];
#pragma unroll
        for (int nt = 0; nt < 4; nt++) {
            mh0 = fmaxf(mh0, fmaxf(sacc[nt][0], sacc[nt][1]));
            mh1 = fmaxf(mh1, fmaxf(sacc[nt][2], sacc[nt][3]));
        }
        mh0 = fmaxf(mh0, __shfl_xor_sync(0xffffffffu, mh0, 1));
        mh0 = fmaxf(mh0, __shfl_xor_sync(0xffffffffu, mh0, 2));
        mh1 = fmaxf(mh1, __shfl_xor_sync(0xffffffffu, mh1, 1));
        mh1 = fmaxf(mh1, __shfl_xor_sync(0xffffffffu, mh1, 2));
        if (t == 0) sts_f2(mxO, mh0, mh1);
        BAR_PAIR(barid);
        float pm0, pm1;
        lds_f2(pm0, pm1, mxP);
        const float m0n = fmaxf(m0, fmaxf(mh0, pm0));
        const float m1n = fmaxf(m1, fmaxf(mh1, pm1));
        bool chg = (m0n > m0) || (m1n > m1);
        if (__any_sync(0xffffffffu, chg)) {
            const float f0 = ex2f(m0 - m0n);
            const float f1 = ex2f(m1 - m1n);
            m0 = m0n; m1 = m1n;
            ls0 *= f0; ls1 *= f1;
#pragma unroll
            for (int i = 0; i < 16; i++) {
                o[i][0] *= f0; o[i][1] *= f0;
                o[i][2] *= f1; o[i][3] *= f1;
            }
        }
        // ---- own u's: build P (common max), publish, PV ----
#pragma unroll
        for (int ul = 0; ul < 2; ul++) {
            const int u = cg * 2 + ul;
            uint32_t A0, A1, A2, A3;
            {
                float p0 = ex2f(sacc[2 * ul][0] - m0), p1 = ex2f(sacc[2 * ul][1] - m0);
                float p2 = ex2f(sacc[2 * ul][2] - m1), p3 = ex2f(sacc[2 * ul][3] - m1);
                A0 = packh2(p1, p0); A1 = packh2(p3, p2);
                p0 = ex2f(sacc[2 * ul + 1][0] - m0); p1 = ex2f(sacc[2 * ul + 1][1] - m0);
                p2 = ex2f(sacc[2 * ul + 1][2] - m1); p3 = ex2f(sacc[2 * ul + 1][3] - m1);
                A2 = packh2(p1, p0); A3 = packh2(p3, p2);
                ls0 += h2sum(A0) + h2sum(A2);
                ls1 += h2sum(A1) + h2sum(A3);
            }
            sts128(pshQ + (uint32_t)(u * 512), A0, A1, A2, A3);
            uint32_t va = vb + (uint32_t)(u * 8192) + (uint32_t)(cg * 4096) + lane16;
#pragma unroll
            for (int p = 0; p < 8; p++) {
                uint32_t v0, v1, v2, v3;
                lds128(v0, v1, v2, v3, va);
                mma_f16(o[2 * p],     A0, A1, A2, A3, v0, v1);
                mma_f16(o[2 * p + 1], A0, A1, A2, A3, v2, v3);
                va += 512;
            }
        }
        BAR_PAIR(barid);
        // ---- partner u's: load shared P, PV ----
#pragma unroll
        for (int ul = 0; ul < 2; ul++) {
            const int u = (1 - cg) * 2 + ul;
            uint32_t A0, A1, A2, A3;
            lds128(A0, A1, A2, A3, pshQ + (uint32_t)(u * 512));
            uint32_t va = vb + (uint32_t)(u * 8192) + (uint32_t)(cg * 4096) + lane16;
#pragma unroll
            for (int p = 0; p < 8; p++) {
                uint32_t v0, v1, v2, v3;
                lds128(v0, v1, v2, v3, va);
                mma_f16(o[2 * p],     A0, A1, A2, A3, v0, v1);
                mma_f16(o[2 * p + 1], A0, A1, A2, A3, v2, v3);
                va += 512;
            }
        }
        // ---- release buffer; producer refills when all 16 warps done ----
        if (l == 0) MB_ARRIVE(mbC + 8 * buf);
        if (tid == 0 && tt + 4 < NT) {
            mb_wait(mbC + 8 * buf, par);
            MB_EXPECT(mbD + 8 * buf, 40960);
            bulkcp(kb, (const char*)g_k + ((size_t)(b * 64 + tt + 4) << 13), 8192, mbD + 8 * buf);
            bulkcp(vb, (const char*)g_v + ((size_t)(b * 64 + tt + 4) << 15), 32768, mbD + 8 * buf);
        }
    }

    // ---------------- epilogue ----------------
    ls0 += __shfl_xor_sync(0xffffffffu, ls0, 1);
    ls0 += __shfl_xor_sync(0xffffffffu, ls0, 2);
    ls1 += __shfl_xor_sync(0xffffffffu, ls1, 1);
    ls1 += __shfl_xor_sync(0xffffffffu, ls1, 2);
    // merge partner-half sums (scale histories identical)
    if (t == 0) sts_f2(sb + SM_LS + (uint32_t)(((qw * 2 + cg) * 8 + l4) * 8), ls0, ls1);
    __syncthreads();
    {
        float pls0, pls1;
        lds_f2(pls0, pls1, sb + SM_LS + (uint32_t)(((qw * 2 + (1 - cg)) * 8 + l4) * 8));
        ls0 += pls0; ls1 += pls1;
    }
    const float inv0 = 1.0f / ls0;
    const float inv1 = 1.0f / ls1;

    float* stage = sm + (SM_BUF / 4);
    const int qlr = 16 * qw + l4;
#pragma unroll 1
    for (int ch = 0; ch < 4; ch++) {
        __syncthreads();
        if (cg == (ch >> 1)) {
#pragma unroll
            for (int k = 0; k < 8; k++) {
                const int nt2 = (ch & 1) * 8 + k;
                const int cloc = k * 8 + 2 * t;
                stage[cloc * 132 + qlr]           = o[nt2][0] * inv0;
                stage[(cloc + 1) * 132 + qlr]     = o[nt2][1] * inv0;
                stage[cloc * 132 + qlr + 8]       = o[nt2][2] * inv1;
                stage[(cloc + 1) * 132 + qlr + 8] = o[nt2][3] * inv1;
            }
        }
        __syncthreads();
        const int cloc2 = tid & 63;
        const int seg   = tid >> 6;
        const int cglob = ch * 64 + cloc2;
        const size_t gbase = ((size_t)(b * C_ + cglob)) * N_ + q0 + seg * 16;
        const float4* xs4 = (const float4*)(x + gbase);
        float4* os4 = (float4*)(out + gbase);
        const float* srow = stage + cloc2 * 132 + seg * 16;
#pragma unroll
        for (int i = 0; i < 4; i++) {
            float4 v = *(const float4*)(srow + 4 * i);
            float4 xv = xs4[i];
            float4 r;
            r.x = xv.x + v.x; r.y = xv.y + v.y; r.z = xv.z + v.z; r.w = xv.w + v.w;
            os4[i] = r;
        }
    }
}

// ====================================================================
extern "C" void kernel_launch(void* const* d_in, const int* in_sizes, int n_in,
                              void* d_out, int out_size)
{
    const float* x  = (const float*)d_in[0];
    const float* wq = (const float*)d_in[1];
    const float* bq = (const float*)d_in[2];
    const float* wk = (const float*)d_in[3];
    const float* bk = (const float*)d_in[4];
    const float* wv = (const float*)d_in[5];
    const float* bv = (const float*)d_in[6];
    float* out = (float*)d_out;

    cudaFuncSetAttribute(proj_kernel, cudaFuncAttributeMaxDynamicSharedMemorySize, PROJ_SMEM_BYTES);
    cudaFuncSetAttribute(attn_mma,    cudaFuncAttributeMaxDynamicSharedMemorySize, ATTN_SMEM_BYTES);

    proj_kernel<<<dim3(N_ / 64, B_), 256, PROJ_SMEM_BYTES>>>(x, wq, bq, wk, bk, wv, bv);
    attn_mma<<<dim3(N_ / TQ, B_), 512, ATTN_SMEM_BYTES>>>(x, out);
}

// round 11
// speedup vs baseline: 4.8725x; 1.9885x over previous
#include <cuda_runtime.h>
#include <cuda_fp16.h>
#include <cstdint>

#define B_  8
#define C_  256
#define N_  4096
#define CQ_ 32
#define TQ  128
#define TJ  64
#define NT  (N_ / TJ)

#define LOG2E 1.4426950408889634f

typedef unsigned long long ull;

// ---------------- gmem scratch: MMA-ready lds128 tile layouts ----------------
__device__ __align__(128) __half g_q[8 * 32 * 8192];
__device__ __align__(128) __half g_k[8 * 64 * 4096];
__device__ __align__(128) __half g_v[8 * 64 * 16384];

// ---------------- PTX helpers ----------------
__device__ __forceinline__ uint32_t su32(const void* p) {
    uint32_t a;
    asm("{ .reg .u64 t; cvta.to.shared.u64 t, %1; cvt.u32.u64 %0, t; }" : "=r"(a) : "l"(p));
    return a;
}
__device__ __forceinline__ float ex2f(float x) {
    float y;
    asm("ex2.approx.ftz.f32 %0, %1;" : "=f"(y) : "f"(x));
    return y;
}
__device__ __forceinline__ void lds128(uint32_t& a, uint32_t& b, uint32_t& c, uint32_t& d,
                                       uint32_t addr) {
    asm volatile("ld.shared.v4.b32 {%0, %1, %2, %3}, [%4];"
                 : "=r"(a), "=r"(b), "=r"(c), "=r"(d) : "r"(addr));
}
__device__ __forceinline__ void sts128(uint32_t addr, uint32_t a, uint32_t b,
                                       uint32_t c, uint32_t d) {
    asm volatile("st.shared.v4.b32 [%0], {%1, %2, %3, %4};"
                 :: "r"(addr), "r"(a), "r"(b), "r"(c), "r"(d) : "memory");
}
__device__ __forceinline__ void sts_f2(uint32_t addr, float a, float b) {
    asm volatile("st.shared.v2.f32 [%0], {%1, %2};" :: "r"(addr), "f"(a), "f"(b) : "memory");
}
__device__ __forceinline__ void lds_f2(float& a, float& b, uint32_t addr) {
    asm volatile("ld.shared.v2.f32 {%0, %1}, [%2];" : "=f"(a), "=f"(b) : "r"(addr));
}
__device__ __forceinline__ void mma_f16(float* c, uint32_t a0, uint32_t a1,
                                        uint32_t a2, uint32_t a3,
                                        uint32_t b0, uint32_t b1) {
    asm volatile(
        "mma.sync.aligned.m16n8k16.row.col.f32.f16.f16.f32 "
        "{%0,%1,%2,%3}, {%4,%5,%6,%7}, {%8,%9}, {%0,%1,%2,%3};"
        : "+f"(c[0]), "+f"(c[1]), "+f"(c[2]), "+f"(c[3])
        : "r"(a0), "r"(a1), "r"(a2), "r"(a3), "r"(b0), "r"(b1));
}
__device__ __forceinline__ uint32_t packh2(float hi, float lo) {
    uint32_t u;
    asm("cvt.rn.f16x2.f32 %0, %1, %2;" : "=r"(u) : "f"(hi), "f"(lo));
    return u;
}
__device__ __forceinline__ float h2sum(uint32_t u) {
    float lo, hi;
    asm("{.reg .b16 l, h;\n mov.b32 {l, h}, %2;\n cvt.f32.f16 %0, l;\n cvt.f32.f16 %1, h;}"
        : "=f"(lo), "=f"(hi) : "r"(u));
    return lo + hi;
}
#define MB_INIT(mb, cnt) \
    asm volatile("mbarrier.init.shared.b64 [%0], %1;" :: "r"(mb), "r"(cnt) : "memory")
#define MB_EXPECT(mb, tx) \
    asm volatile("mbarrier.arrive.expect_tx.shared.b64 _, [%0], %1;" :: "r"(mb), "r"(tx) : "memory")
#define MB_ARRIVE(mb) \
    asm volatile("mbarrier.arrive.shared.b64 _, [%0];" :: "r"(mb) : "memory")
__device__ __forceinline__ void mb_wait(uint32_t mb, uint32_t parity) {
    asm volatile(
        "{\n .reg .pred P;\n"
        "W%=:\n"
        " mbarrier.try_wait.parity.acquire.cta.shared::cta.b64 P, [%0], %1, 0x989680;\n"
        " @P bra D%=;\n"
        " bra W%=;\n"
        "D%=:\n}"
        :: "r"(mb), "r"(parity) : "memory");
}
__device__ __forceinline__ void bulkcp(uint32_t dst, const void* src, uint32_t bytes, uint32_t mbar) {
    asm volatile(
        "cp.async.bulk.shared::cluster.global.mbarrier::complete_tx::bytes [%0], [%1], %2, [%3];"
        :: "r"(dst), "l"(src), "r"(bytes), "r"(mbar) : "memory");
}
#define BAR_PAIR(id) \
    asm volatile("bar.sync %0, 64;" :: "r"(id) : "memory")

// fragment slot: element e (0..15 within k16) -> slot (t = slot>>2, q = slot&3)
__device__ __forceinline__ int sig(int e) {
    return (e < 8) ? ((e >> 1) * 4 + (e & 1)) : (((e & 7) >> 1) * 4 + 2 + (e & 1));
}

// ---------------- packed f32x2 (proj compute) ----------------
__device__ __forceinline__ ull ffma2(ull a, ull b, ull c) {
    ull d; asm("fma.rn.f32x2 %0, %1, %2, %3;" : "=l"(d) : "l"(a), "l"(b), "l"(c)); return d;
}
__device__ __forceinline__ ull pack2(float x, float y) {
    ull r; asm("mov.b64 %0, {%1, %2};" : "=l"(r) : "f"(x), "f"(y)); return r;
}
__device__ __forceinline__ float2 unpack2(ull v) {
    float2 f; asm("mov.b64 {%0, %1}, %2;" : "=f"(f.x), "=f"(f.y) : "l"(v)); return f;
}

// ====================================================================
// Projection kernel (unchanged).
// ====================================================================
#define PROJ_SMEM_FLOATS (2048 + 32*258 + 32*36 + 32*36)
#define PROJ_SMEM_BYTES  (PROJ_SMEM_FLOATS * 4)

__global__ void __launch_bounds__(256) proj_kernel(
    const float* __restrict__ x,
    const float* __restrict__ wq, const float* __restrict__ bq,
    const float* __restrict__ wk, const float* __restrict__ bk,
    const float* __restrict__ wv, const float* __restrict__ bv)
{
    extern __shared__ float sm[];
    float* xs  = sm;
    float* wvs = sm + 2048;
    float* wqs = wvs + 32 * 258;
    float* wks = wqs + 32 * 36;

    const int tid = threadIdx.x;
    const int n   = tid & 63;
    const int grp = tid >> 6;
    const int b   = blockIdx.y;
    const int n0  = blockIdx.x * 64;

    ull accv[32]; ull accq[4], acck[4];
#pragma unroll
    for (int i = 0; i < 32; i++) accv[i] = 0ull;
#pragma unroll
    for (int i = 0; i < 4; i++) { accq[i] = 0ull; acck[i] = 0ull; }

    for (int kc = 0; kc < 8; kc++) {
        __syncthreads();
        {
            const float4* xg = (const float4*)(x + ((size_t)b * C_ + kc * 32) * N_ + n0);
            float4* xs4 = (float4*)xs;
            for (int i = tid; i < 32 * 16; i += 256) {
                int ci = i >> 4, n4 = i & 15;
                xs4[ci * 16 + n4] = xg[(size_t)ci * (N_ / 4) + n4];
            }
        }
        for (int i = tid; i < 256 * 32; i += 256) {
            int co = i >> 5, ci = i & 31;
            wvs[ci * 258 + co] = wv[co * C_ + kc * 32 + ci];
        }
        for (int i = tid; i < 32 * 32; i += 256) {
            int d = i >> 5, ci = i & 31;
            wqs[ci * 36 + d] = wq[d * C_ + kc * 32 + ci];
            wks[ci * 36 + d] = wk[d * C_ + kc * 32 + ci];
        }
        __syncthreads();

#pragma unroll 4
        for (int ci = 0; ci < 32; ci++) {
            float xv = xs[ci * 64 + n];
            ull  xv2 = pack2(xv, xv);
            const ull* wr  = (const ull*)&wvs[ci * 258 + grp * 64];
#pragma unroll
            for (int i = 0; i < 32; i++) accv[i] = ffma2(wr[i], xv2, accv[i]);
            const ull* wrq = (const ull*)&wqs[ci * 36 + grp * 8];
            const ull* wrk = (const ull*)&wks[ci * 36 + grp * 8];
#pragma unroll
            for (int i = 0; i < 4; i++) {
                accq[i] = ffma2(wrq[i], xv2, accq[i]);
                acck[i] = ffma2(wrk[i], xv2, acck[i]);
            }
        }
    }

    const int np   = n0 + n;
    const int tile = np >> 6;
    const int j    = np & 63;
    const int qt   = np >> 7;
    const int r    = np & 127;
    const size_t kBase = ((size_t)(b * 64 + tile)) << 12;
    const size_t vBase = ((size_t)(b * 64 + tile)) << 14;
    const size_t qBase = ((size_t)(b * 32 + qt))   << 13;

    {
        const int u  = j >> 4;
        const int sl = sig(j & 15);
        const int tV = sl >> 2, qV = sl & 3;
        const size_t vb2 = vBase + (size_t)u * 4096 + tV * 8 + qV;
#pragma unroll
        for (int i = 0; i < 32; i++) {
            float2 a = unpack2(accv[i]);
            int c0 = grp * 64 + 2 * i;
            size_t o0 = vb2 + (size_t)(c0 >> 4) * 256 + (size_t)(c0 & 7) * 32
                      + (size_t)((c0 >> 3) & 1) * 4;
            int c1 = c0 + 1;
            size_t o1 = vb2 + (size_t)(c1 >> 4) * 256 + (size_t)(c1 & 7) * 32
                      + (size_t)((c1 >> 3) & 1) * 4;
            g_v[o0] = __float2half_rn(a.x + __ldg(&bv[c0]));
            g_v[o1] = __float2half_rn(a.y + __ldg(&bv[c1]));
        }
    }
    {
        const int knt = j >> 3, l4k = j & 7;
        const int qw = r >> 4, rr = r & 15;
        const int l4q = rr & 7, rowsel = rr >> 3;
#pragma unroll
        for (int i = 0; i < 4; i++) {
            float2 aq = unpack2(accq[i]);
            float2 ak = unpack2(acck[i]);
#pragma unroll
            for (int e2 = 0; e2 < 2; e2++) {
                const int d  = grp * 8 + 2 * i + e2;
                const int kg = d >> 4;
                const int sl = sig(d & 15);
                const int tt = sl >> 2, qq = sl & 3;
                float v = ((e2 ? aq.y : aq.x) + __ldg(&bq[d])) * LOG2E;
                __half h  = __float2half_rn(v);
                __half lo = __float2half_rn(v - __half2float(h));
                size_t qo = qBase + (size_t)kg * 2048 + (size_t)qw * 256
                          + (size_t)(l4q * 4 + tt) * 8 + rowsel * 4 + qq;
                g_q[qo]        = h;
                g_q[qo + 4096] = lo;
                v  = (e2 ? ak.y : ak.x) + __ldg(&bk[d]);
                h  = __float2half_rn(v);
                lo = __float2half_rn(v - __half2float(h));
                size_t ko = kBase + (size_t)knt * 256
                          + (size_t)(l4k * 4 + tt) * 8 + kg * 4 + qq;
                g_k[ko]        = h;
                g_k[ko + 2048] = lo;
            }
        }
    }
}

// ====================================================================
// fp16 flash attention. S grid: (qw 8, cg 2). PV grid: (qp 4, ch 4)
// — 32 queries x 64 channels per warp, P + rescale factors via SMEM.
// ====================================================================
#define SM_BUF   0
#define BUF_SZ   40960                 /* 4 bufs: K 8KB + V 32KB      */
#define SM_PSH   163840                /* P publish, x2: [qw][u][512B]*/
#define SM_F     196608                /* rescale f,  x2: [qw][l4][8B]*/
#define SM_MX    197632                /* pair max exchange, 1KB      */
#define SM_LS    198656                /* half-sums, 1KB              */
#define SM_LS2   199680                /* final per-row ls, 512B      */
#define SM_MBAR  200192                /* mbD x4, mbC x4              */
#define ATTN_SMEM_BYTES 200448

__global__ void __launch_bounds__(512, 1) attn_mma(
    const float* __restrict__ x, float* __restrict__ out)
{
    extern __shared__ float sm[];
    const uint32_t sb = su32(sm);
    const int tid = threadIdx.x;
    const int w   = tid >> 5;
    const int qw  = w & 7;           // S: query band
    const int cg  = w >> 3;          // S: key half
    const int qp  = w & 3;           // PV: 32-query block (qbands 2qp, 2qp+1)
    const int ch  = w >> 2;          // PV: 64-channel quarter
    const int l   = tid & 31;
    const int l4  = l >> 2;
    const int t   = l & 3;
    const int b   = blockIdx.y;
    const int qt  = blockIdx.x;
    const int q0  = qt * TQ;
    const uint32_t lane16 = (uint32_t)l * 16;
    const int barid = 1 + qw;

    const uint32_t mbD = sb + SM_MBAR;
    const uint32_t mbC = sb + SM_MBAR + 32;
    const uint32_t mxO = sb + SM_MX + (uint32_t)(((qw * 2 + cg) * 8 + l4) * 8);
    const uint32_t mxP = sb + SM_MX + (uint32_t)(((qw * 2 + (1 - cg)) * 8 + l4) * 8);

    if (tid == 0) {
#pragma unroll
        for (int i = 0; i < 4; i++) { MB_INIT(mbD + 8 * i, 1); MB_INIT(mbC + 8 * i, 16); }
    }
    __syncthreads();

    if (tid == 0) {
#pragma unroll
        for (int i = 0; i < 4; i++) {
            MB_EXPECT(mbD + 8 * i, 40960);
            bulkcp(sb + SM_BUF + i * BUF_SZ,
                   (const char*)g_k + ((size_t)(b * 64 + i) << 13), 8192, mbD + 8 * i);
            bulkcp(sb + SM_BUF + i * BUF_SZ + 8192,
                   (const char*)g_v + ((size_t)(b * 64 + i) << 15), 32768, mbD + 8 * i);
        }
    }

    // ---- Q hi+lo fragments: direct LDG.128 from gmem (fragment-shaped) ----
    uint32_t qh[2][4], ql[2][4];
    {
        const __half* qgm = g_q + ((size_t)(b * 32 + qt) << 13);
#pragma unroll
        for (int kg = 0; kg < 2; kg++) {
            uint4 v = *(const uint4*)(qgm + kg * 2048 + qw * 256 + l * 8);
            qh[kg][0] = v.x; qh[kg][1] = v.z; qh[kg][2] = v.y; qh[kg][3] = v.w;
            uint4 u2 = *(const uint4*)(qgm + 4096 + kg * 2048 + qw * 256 + l * 8);
            ql[kg][0] = u2.x; ql[kg][1] = u2.z; ql[kg][2] = u2.y; ql[kg][3] = u2.w;
        }
    }

    float o[16][4];
#pragma unroll
    for (int i = 0; i < 16; i++)
#pragma unroll
        for (int e = 0; e < 4; e++) o[i][e] = 0.f;
    float m0 = -1e30f, m1 = -1e30f, ls0 = 0.f, ls1 = 0.f;

    for (int tt = 0; tt < NT; tt++) {
        const int buf = tt & 3;
        const uint32_t kb = sb + SM_BUF + (uint32_t)buf * BUF_SZ;
        const uint32_t vb = kb + 8192;
        const uint32_t par = (uint32_t)((tt >> 2) & 1);
        const uint32_t pshB = sb + SM_PSH + (uint32_t)(tt & 1) * 16384;
        const uint32_t fB   = sb + SM_F   + (uint32_t)(tt & 1) * 512;
        mb_wait(mbD + 8 * buf, par);

        // ---- S for own (qw x 32-key half), hi/lo 3-pass ----
        float sacc[4][4];
        const uint32_t kaBase = kb + (uint32_t)(cg * 2048) + lane16;
#pragma unroll
        for (int nt = 0; nt < 4; nt++) {
#pragma unroll
            for (int e = 0; e < 4; e++) sacc[nt][e] = 0.f;
            const uint32_t ka = kaBase + (uint32_t)(nt * 512);
            uint32_t h0, h1, h2, h3, g0, g1, g2, g3;
            lds128(h0, h1, h2, h3, ka);
            lds128(g0, g1, g2, g3, ka + 4096);
            mma_f16(sacc[nt], qh[0][0], qh[0][1], qh[0][2], qh[0][3], h0, h1);
            mma_f16(sacc[nt], qh[1][0], qh[1][1], qh[1][2], qh[1][3], h2, h3);
            mma_f16(sacc[nt], ql[0][0], ql[0][1], ql[0][2], ql[0][3], h0, h1);
            mma_f16(sacc[nt], ql[1][0], ql[1][1], ql[1][2], ql[1][3], h2, h3);
            mma_f16(sacc[nt], qh[0][0], qh[0][1], qh[0][2], qh[0][3], g0, g1);
            mma_f16(sacc[nt], qh[1][0], qh[1][1], qh[1][2], qh[1][3], g2, g3);
        }
        // ---- own-half max (quad-reduced), exchange with pair partner ----
        float mh0 = sacc[0][0], mh1 = sacc[0][2];
#pragma unroll
        for (int nt = 0; nt < 4; nt++) {
            mh0 = fmaxf(mh0, fmaxf(sacc[nt][0], sacc[nt][1]));
            mh1 = fmaxf(mh1, fmaxf(sacc[nt][2], sacc[nt][3]));
        }
        mh0 = fmaxf(mh0, __shfl_xor_sync(0xffffffffu, mh0, 1));
        mh0 = fmaxf(mh0, __shfl_xor_sync(0xffffffffu, mh0, 2));
        mh1 = fmaxf(mh1, __shfl_xor_sync(0xffffffffu, mh1, 1));
        mh1 = fmaxf(mh1, __shfl_xor_sync(0xffffffffu, mh1, 2));
        if (t == 0) sts_f2(mxO, mh0, mh1);
        BAR_PAIR(barid);
        float pm0, pm1;
        lds_f2(pm0, pm1, mxP);
        const float m0n = fmaxf(m0, fmaxf(mh0, pm0));
        const float m1n = fmaxf(m1, fmaxf(mh1, pm1));
        const float f0 = ex2f(m0 - m0n);
        const float f1 = ex2f(m1 - m1n);
        m0 = m0n; m1 = m1n;
        ls0 *= f0; ls1 *= f1;
        if (cg == 0 && t == 0) sts_f2(fB + (uint32_t)(qw * 64 + l4 * 8), f0, f1);

        // ---- P build + publish (own 2 u's; common max across pair) ----
#pragma unroll
        for (int ul = 0; ul < 2; ul++) {
            const int u = cg * 2 + ul;
            uint32_t A0, A1, A2, A3;
            {
                float p0 = ex2f(sacc[2 * ul][0] - m0), p1 = ex2f(sacc[2 * ul][1] - m0);
                float p2 = ex2f(sacc[2 * ul][2] - m1), p3 = ex2f(sacc[2 * ul][3] - m1);
                A0 = packh2(p1, p0); A1 = packh2(p3, p2);
                p0 = ex2f(sacc[2 * ul + 1][0] - m0); p1 = ex2f(sacc[2 * ul + 1][1] - m0);
                p2 = ex2f(sacc[2 * ul + 1][2] - m1); p3 = ex2f(sacc[2 * ul + 1][3] - m1);
                A2 = packh2(p1, p0); A3 = packh2(p3, p2);
                ls0 += h2sum(A0) + h2sum(A2);
                ls1 += h2sum(A1) + h2sum(A3);
            }
            sts128(pshB + (uint32_t)(qw * 2048 + u * 512) + lane16, A0, A1, A2, A3);
        }
        __syncthreads();

        // ---- consumer: rescale o by published f for its 2 qbands ----
        {
            float g0a, g1a, g0b, g1b;
            lds_f2(g0a, g1a, fB + (uint32_t)((2 * qp) * 64 + l4 * 8));
            lds_f2(g0b, g1b, fB + (uint32_t)((2 * qp + 1) * 64 + l4 * 8));
#pragma unroll
            for (int i = 0; i < 8; i++) {
                o[i][0] *= g0a; o[i][1] *= g0a; o[i][2] *= g1a; o[i][3] *= g1a;
            }
#pragma unroll
            for (int i = 8; i < 16; i++) {
                o[i][0] *= g0b; o[i][1] *= g0b; o[i][2] *= g1b; o[i][3] *= g1b;
            }
        }
        // ---- PV: 32 queries (2 qbands) x 64 channels (quarter ch) ----
#pragma unroll
        for (int u = 0; u < 4; u++) {
            uint32_t A0, A1, A2, A3, B0, B1, B2, B3;
            lds128(A0, A1, A2, A3, pshB + (uint32_t)((2 * qp) * 2048 + u * 512) + lane16);
            lds128(B0, B1, B2, B3, pshB + (uint32_t)((2 * qp + 1) * 2048 + u * 512) + lane16);
            uint32_t va = vb + (uint32_t)(u * 8192 + ch * 2048) + lane16;
#pragma unroll
            for (int p = 0; p < 4; p++) {
                uint32_t v0, v1, v2, v3;
                lds128(v0, v1, v2, v3, va);
                mma_f16(o[p * 2],         A0, A1, A2, A3, v0, v1);
                mma_f16(o[p * 2 + 1],     A0, A1, A2, A3, v2, v3);
                mma_f16(o[8 + p * 2],     B0, B1, B2, B3, v0, v1);
                mma_f16(o[8 + p * 2 + 1], B0, B1, B2, B3, v2, v3);
                va += 512;
            }
        }
        // ---- release buffer; tid0 refills tt+4 ----
        if (l == 0) MB_ARRIVE(mbC + 8 * buf);
        if (tid == 0 && tt + 4 < NT) {
            mb_wait(mbC + 8 * buf, par);
            MB_EXPECT(mbD + 8 * buf, 40960);
            bulkcp(kb, (const char*)g_k + ((size_t)(b * 64 + tt + 4) << 13), 8192, mbD + 8 * buf);
            bulkcp(vb, (const char*)g_v + ((size_t)(b * 64 + tt + 4) << 15), 32768, mbD + 8 * buf);
        }
    }

    // ---------------- epilogue ----------------
    ls0 += __shfl_xor_sync(0xffffffffu, ls0, 1);
    ls0 += __shfl_xor_sync(0xffffffffu, ls0, 2);
    ls1 += __shfl_xor_sync(0xffffffffu, ls1, 1);
    ls1 += __shfl_xor_sync(0xffffffffu, ls1, 2);
    if (t == 0) sts_f2(sb + SM_LS + (uint32_t)(((qw * 2 + cg) * 8 + l4) * 8), ls0, ls1);
    __syncthreads();
    {
        float p0, p1;
        lds_f2(p0, p1, sb + SM_LS + (uint32_t)(((qw * 2 + (1 - cg)) * 8 + l4) * 8));
        ls0 += p0; ls1 += p1;
    }
    if (cg == 0 && t == 0) {
        sm[(SM_LS2 >> 2) + qw * 16 + l4]     = ls0;
        sm[(SM_LS2 >> 2) + qw * 16 + l4 + 8] = ls1;
    }
    __syncthreads();
    float inv0a, inv1a, inv0b, inv1b;
    {
        const float* lsf = sm + (SM_LS2 >> 2);
        inv0a = 1.0f / lsf[(2 * qp) * 16 + l4];
        inv1a = 1.0f / lsf[(2 * qp) * 16 + l4 + 8];
        inv0b = 1.0f / lsf[(2 * qp + 1) * 16 + l4];
        inv1b = 1.0f / lsf[(2 * qp + 1) * 16 + l4 + 8];
    }

    float* stage = sm;   // reuse buffer region (all tiles consumed)
#pragma unroll 1
    for (int ch2 = 0; ch2 < 4; ch2++) {
        __syncthreads();
        if (ch == ch2) {
#pragma unroll
            for (int qb = 0; qb < 2; qb++) {
                const int q = (2 * qp + qb) * 16 + l4;
                const float i0 = qb ? inv0b : inv0a;
                const float i1 = qb ? inv1b : inv1a;
#pragma unroll
                for (int k = 0; k < 8; k++) {      // k = p*2+s
                    const int i = qb * 8 + k;
                    const int cloc = k * 8 + 2 * t;
                    stage[cloc * 132 + q]           = o[i][0] * i0;
                    stage[(cloc + 1) * 132 + q]     = o[i][1] * i0;
                    stage[cloc * 132 + q + 8]       = o[i][2] * i1;
                    stage[(cloc + 1) * 132 + q + 8] = o[i][3] * i1;
                }
            }
        }
        __syncthreads();
        const int cloc2 = tid & 63;
        const int seg   = tid >> 6;
        const int cglob = ch2 * 64 + cloc2;
        const size_t gbase = ((size_t)(b * C_ + cglob)) * N_ + q0 + seg * 16;
        const float4* xs4 = (const float4*)(x + gbase);
        float4* os4 = (float4*)(out + gbase);
        const float* srow = stage + cloc2 * 132 + seg * 16;
#pragma unroll
        for (int i = 0; i < 4; i++) {
            float4 v = *(const float4*)(srow + 4 * i);
            float4 xv = xs4[i];
            float4 r;
            r.x = xv.x + v.x; r.y = xv.y + v.y; r.z = xv.z + v.z; r.w = xv.w + v.w;
            os4[i] = r;
        }
    }
}

// ====================================================================
extern "C" void kernel_launch(void* const* d_in, const int* in_sizes, int n_in,
                              void* d_out, int out_size)
{
    const float* x  = (const float*)d_in[0];
    const float* wq = (const float*)d_in[1];
    const float* bq = (const float*)d_in[2];
    const float* wk = (const float*)d_in[3];
    const float* bk = (const float*)d_in[4];
    const float* wv = (const float*)d_in[5];
    const float* bv = (const float*)d_in[6];
    float* out = (float*)d_out;

    cudaFuncSetAttribute(proj_kernel, cudaFuncAttributeMaxDynamicSharedMemorySize, PROJ_SMEM_BYTES);
    cudaFuncSetAttribute(attn_mma,    cudaFuncAttributeMaxDynamicSharedMemorySize, ATTN_SMEM_BYTES);

    proj_kernel<<<dim3(N_ / 64, B_), 256, PROJ_SMEM_BYTES>>>(x, wq, bq, wk, bk, wv, bv);
    attn_mma<<<dim3(N_ / TQ, B_), 512, ATTN_SMEM_BYTES>>>(x, out);
}

// round 13
// speedup vs baseline: 8.3599x; 1.7157x over previous
#include <cuda_runtime.h>
#include <cuda_fp16.h>
#include <cstdint>

#define B_  8
#define C_  256
#define N_  4096
#define CQ_ 32
#define TQ  128
#define TJ  64
#define NT  (N_ / TJ)

#define LOG2E 1.4426950408889634f

// ---------------- gmem scratch: MMA-ready lds128 tile layouts ----------------
__device__ __align__(128) __half g_q[8 * 32 * 8192];
__device__ __align__(128) __half g_k[8 * 64 * 4096];
__device__ __align__(128) __half g_v[8 * 64 * 16384];
// W A-fragments: hi = uint4[0..10239], lo = uint4[10240..20479]
__device__ __align__(128) __half g_wA[2 * 20 * 16 * 32 * 8];

// ---------------- PTX helpers ----------------
__device__ __forceinline__ uint32_t su32(const void* p) {
    uint32_t a;
    asm("{ .reg .u64 t; cvta.to.shared.u64 t, %1; cvt.u32.u64 %0, t; }" : "=r"(a) : "l"(p));
    return a;
}
__device__ __forceinline__ float ex2f(float x) {
    float y;
    asm("ex2.approx.ftz.f32 %0, %1;" : "=f"(y) : "f"(x));
    return y;
}
__device__ __forceinline__ void lds128(uint32_t& a, uint32_t& b, uint32_t& c, uint32_t& d,
                                       uint32_t addr) {
    asm volatile("ld.shared.v4.b32 {%0, %1, %2, %3}, [%4];"
                 : "=r"(a), "=r"(b), "=r"(c), "=r"(d) : "r"(addr));
}
__device__ __forceinline__ void sts128(uint32_t addr, uint32_t a, uint32_t b,
                                       uint32_t c, uint32_t d) {
    asm volatile("st.shared.v4.b32 [%0], {%1, %2, %3, %4};"
                 :: "r"(addr), "r"(a), "r"(b), "r"(c), "r"(d) : "memory");
}
__device__ __forceinline__ void sts_f2(uint32_t addr, float a, float b) {
    asm volatile("st.shared.v2.f32 [%0], {%1, %2};" :: "r"(addr), "f"(a), "f"(b) : "memory");
}
__device__ __forceinline__ void lds_f2(float& a, float& b, uint32_t addr) {
    asm volatile("ld.shared.v2.f32 {%0, %1}, [%2];" : "=f"(a), "=f"(b) : "r"(addr));
}
__device__ __forceinline__ void mma_f16(float* c, uint32_t a0, uint32_t a1,
                                        uint32_t a2, uint32_t a3,
                                        uint32_t b0, uint32_t b1) {
    asm volatile(
        "mma.sync.aligned.m16n8k16.row.col.f32.f16.f16.f32 "
        "{%0,%1,%2,%3}, {%4,%5,%6,%7}, {%8,%9}, {%0,%1,%2,%3};"
        : "+f"(c[0]), "+f"(c[1]), "+f"(c[2]), "+f"(c[3])
        : "r"(a0), "r"(a1), "r"(a2), "r"(a3), "r"(b0), "r"(b1));
}
__device__ __forceinline__ uint32_t packh2(float hi, float lo) {
    uint32_t u;
    asm("cvt.rn.f16x2.f32 %0, %1, %2;" : "=r"(u) : "f"(hi), "f"(lo));
    return u;
}
__device__ __forceinline__ uint32_t pack2h(__half hi, __half lo) {
    return ((uint32_t)__half_as_ushort(hi) << 16) | __half_as_ushort(lo);
}
__device__ __forceinline__ float h2sum(uint32_t u) {
    float lo, hi;
    asm("{.reg .b16 l, h;\n mov.b32 {l, h}, %2;\n cvt.f32.f16 %0, l;\n cvt.f32.f16 %1, h;}"
        : "=f"(lo), "=f"(hi) : "r"(u));
    return lo + hi;
}
#define MB_INIT(mb, cnt) \
    asm volatile("mbarrier.init.shared.b64 [%0], %1;" :: "r"(mb), "r"(cnt) : "memory")
#define MB_EXPECT(mb, tx) \
    asm volatile("mbarrier.arrive.expect_tx.shared.b64 _, [%0], %1;" :: "r"(mb), "r"(tx) : "memory")
#define MB_ARRIVE(mb) \
    asm volatile("mbarrier.arrive.shared.b64 _, [%0];" :: "r"(mb) : "memory")
__device__ __forceinline__ void mb_wait(uint32_t mb, uint32_t parity) {
    asm volatile(
        "{\n .reg .pred P;\n"
        "W%=:\n"
        " mbarrier.try_wait.parity.acquire.cta.shared::cta.b64 P, [%0], %1, 0x989680;\n"
        " @P bra D%=;\n"
        " bra W%=;\n"
        "D%=:\n}"
        :: "r"(mb), "r"(parity) : "memory");
}
__device__ __forceinline__ void bulkcp(uint32_t dst, const void* src, uint32_t bytes, uint32_t mbar) {
    asm volatile(
        "cp.async.bulk.shared::cluster.global.mbarrier::complete_tx::bytes [%0], [%1], %2, [%3];"
        :: "r"(dst), "l"(src), "r"(bytes), "r"(mbar) : "memory");
}
#define BAR_PAIR(id) \
    asm volatile("bar.sync %0, 64;" :: "r"(id) : "memory")

// ====================================================================
// W prep: bake [wv;wq;wk] into A-fragment hi/lo layout; wq scaled LOG2E.
// ====================================================================
__global__ void __launch_bounds__(512) wprep(
    const float* __restrict__ wv, const float* __restrict__ wq,
    const float* __restrict__ wk)
{
    const int dt = blockIdx.x;
    const int tid = threadIdx.x;
    const int kc = tid >> 5, ln = tid & 31;
    const int l4 = ln >> 2, t = ln & 3;

    const float* W;
    int rbase;
    float scale = 1.0f;
    if (dt < 16)      { W = wv; rbase = dt * 16; }
    else if (dt < 18) { W = wq; rbase = (dt - 16) * 16; scale = LOG2E; }
    else              { W = wk; rbase = (dt - 18) * 16; }

    const int r0 = rbase + l4, r1 = r0 + 8;
    const int c0 = kc * 16 + 2 * t;
    float f[8];
    f[0] = W[r0 * 256 + c0]     * scale;  f[1] = W[r0 * 256 + c0 + 1] * scale;
    f[2] = W[r1 * 256 + c0]     * scale;  f[3] = W[r1 * 256 + c0 + 1] * scale;
    f[4] = W[r0 * 256 + c0 + 8] * scale;  f[5] = W[r0 * 256 + c0 + 9] * scale;
    f[6] = W[r1 * 256 + c0 + 8] * scale;  f[7] = W[r1 * 256 + c0 + 9] * scale;

    __half h[8]; float l[8];
#pragma unroll
    for (int i = 0; i < 8; i++) {
        h[i] = __float2half_rn(f[i]);
        l[i] = f[i] - __half2float(h[i]);
    }
    uint4 hiw, low;
    hiw.x = pack2h(h[1], h[0]); hiw.y = pack2h(h[3], h[2]);
    hiw.z = pack2h(h[5], h[4]); hiw.w = pack2h(h[7], h[6]);
    low.x = packh2(l[1], l[0]); low.y = packh2(l[3], l[2]);
    low.z = packh2(l[5], l[4]); low.w = packh2(l[7], l[6]);
    uint4* dst = (uint4*)g_wA + (dt * 512 + kc * 32 + ln);
    dst[0]     = hiw;
    dst[10240] = low;     // FIX: lo region starts after 20*512=10240 uint4s
}

// ====================================================================
// proj_mma: out = W_all @ x per 64-column block; fp16 hi/lo 3-pass MMA.
// ====================================================================
#define RAW_STRIDE 68
#define SM_RAW  0
#define SM_FRAG 17408   /* floats */
#define PROJ2_SMEM_BYTES ((17408 + 16384) * 4)

__global__ void __launch_bounds__(640, 1) proj_mma(
    const float* __restrict__ x,
    const float* __restrict__ bq, const float* __restrict__ bk,
    const float* __restrict__ bv)
{
    extern __shared__ float sm[];
    const int tid = threadIdx.x;
    const int b  = blockIdx.y;
    const int bx = blockIdx.x;
    const int w  = tid >> 5, l = tid & 31;
    const int l4 = l >> 2, t = l & 3;

    // ---- phase 0: x -> raw[c][RAW_STRIDE] ----
    {
        const float4* xg = (const float4*)(x + ((size_t)b * C_) * N_ + bx * 64);
        for (int idx = tid; idx < 4096; idx += 640) {
            int c = idx >> 4, nI = idx & 15;
            float4 v = xg[(size_t)c * (N_ / 4) + nI];
            *(float4*)(sm + SM_RAW + c * RAW_STRIDE + nI * 4) = v;
        }
    }
    __syncthreads();
    // ---- phase 1: fp32 -> fp16 hi/lo B fragments ----
    for (int idx = tid; idx < 4096; idx += 640) {
        int kc = idx >> 8, nf = (idx >> 5) & 7, ln = idx & 31;
        int l4p = ln >> 2, tp = ln & 3;
        int n = nf * 8 + l4p, c = kc * 16 + 2 * tp;
        const float* rp = sm + SM_RAW + n;
        float f0 = rp[c * RAW_STRIDE];
        float f1 = rp[(c + 1) * RAW_STRIDE];
        float f2 = rp[(c + 8) * RAW_STRIDE];
        float f3 = rp[(c + 9) * RAW_STRIDE];
        __half h0 = __float2half_rn(f0), h1 = __float2half_rn(f1);
        __half h2 = __float2half_rn(f2), h3 = __float2half_rn(f3);
        uint4 o;
        o.x = pack2h(h1, h0);
        o.y = pack2h(h3, h2);
        o.z = packh2(f1 - __half2float(h1), f0 - __half2float(h0));
        o.w = packh2(f3 - __half2float(h3), f2 - __half2float(h2));
        *(uint4*)(sm + SM_FRAG + ((kc * 8 + nf) * 32 + ln) * 4) = o;
    }
    __syncthreads();

    // ---- phase 2: MMA, warp w = d-tile ----
    float acc[8][4];
#pragma unroll
    for (int i = 0; i < 8; i++)
#pragma unroll
        for (int e = 0; e < 4; e++) acc[i][e] = 0.f;

    const uint4* wAhi = (const uint4*)g_wA + (w * 512 + l);
    for (int kc = 0; kc < 16; kc++) {
        uint4 ah = __ldg(wAhi + kc * 32);
        uint4 al = __ldg(wAhi + kc * 32 + 10240);   // FIX: lo at +10240 uint4
        const uint4* fb = (const uint4*)(sm + SM_FRAG) + (kc * 8) * 32 + l;
#pragma unroll
        for (int nf = 0; nf < 8; nf++) {
            uint4 xb = fb[nf * 32];
            mma_f16(acc[nf], ah.x, ah.y, ah.z, ah.w, xb.x, xb.y);
            mma_f16(acc[nf], al.x, al.y, al.z, al.w, xb.x, xb.y);
            mma_f16(acc[nf], ah.x, ah.y, ah.z, ah.w, xb.z, xb.w);
        }
    }

    // ---- phase 3: scatter to attn layouts ----
    if (w < 16) {
        const float bv0 = __ldg(bv + w * 16 + l4);
        const float bv1 = __ldg(bv + w * 16 + l4 + 8);
        __half* vout = g_v + (((size_t)(b * 64 + bx)) << 14) + w * 256 + l4 * 32 + t * 8;
#pragma unroll
        for (int u = 0; u < 4; u++) {
            const int nA = 2 * u, nB = 2 * u + 1;
            uint4 o;
            o.x = packh2(acc[nA][1] + bv0, acc[nA][0] + bv0);
            o.y = packh2(acc[nB][1] + bv0, acc[nB][0] + bv0);
            o.z = packh2(acc[nA][3] + bv1, acc[nA][2] + bv1);
            o.w = packh2(acc[nB][3] + bv1, acc[nB][2] + bv1);
            *(uint4*)(vout + u * 4096) = o;
        }
    } else {
        float* stg = sm + SM_RAW + (w - 16) * 1100;
#pragma unroll
        for (int nf = 0; nf < 8; nf++) {
            stg[l4 * RAW_STRIDE + nf * 8 + 2 * t]           = acc[nf][0];
            stg[l4 * RAW_STRIDE + nf * 8 + 2 * t + 1]       = acc[nf][1];
            stg[(l4 + 8) * RAW_STRIDE + nf * 8 + 2 * t]     = acc[nf][2];
            stg[(l4 + 8) * RAW_STRIDE + nf * 8 + 2 * t + 1] = acc[nf][3];
        }
        __syncwarp();
        const int kg  = (w - 16) & 1;
        const bool isQ = (w < 18);
        const float* bias = isQ ? bq : bk;
        const float bsc = isQ ? LOG2E : 1.0f;
        __half *outh, *outl;
        if (isQ) {
            outh = g_q + (((size_t)(b * 32 + (bx >> 1))) << 13) + kg * 2048;
            outl = outh + 4096;
        } else {
            outh = g_k + (((size_t)(b * 64 + bx)) << 12);
            outl = outh + 2048;
        }
#pragma unroll
        for (int i = 0; i < 8; i++) {
            const int tidx = i * 32 + l;
            const int n = tidx >> 2, tt = tidx & 3;
            const int d0 = kg * 16 + 2 * tt;
            float f0 = stg[(2 * tt) * RAW_STRIDE + n]     + bsc * __ldg(bias + d0);
            float f1 = stg[(2 * tt + 1) * RAW_STRIDE + n] + bsc * __ldg(bias + d0 + 1);
            float f2 = stg[(2 * tt + 8) * RAW_STRIDE + n] + bsc * __ldg(bias + d0 + 8);
            float f3 = stg[(2 * tt + 9) * RAW_STRIDE + n] + bsc * __ldg(bias + d0 + 9);
            __half h0 = __float2half_rn(f0), h1 = __float2half_rn(f1);
            __half h2 = __float2half_rn(f2), h3 = __float2half_rn(f3);
            uint2 hw, lw;
            hw.x = pack2h(h1, h0);
            hw.y = pack2h(h3, h2);
            lw.x = packh2(f1 - __half2float(h1), f0 - __half2float(h0));
            lw.y = packh2(f3 - __half2float(h3), f2 - __half2float(h2));
            uint32_t off;
            if (isQ) {
                const int r = (bx & 1) * 64 + n;
                off = (uint32_t)((r >> 4) * 256 + (r & 7) * 32 + tt * 8 + ((r >> 3) & 1) * 4);
            } else {
                off = (uint32_t)((n >> 3) * 256 + (n & 7) * 32 + tt * 8 + kg * 4);
            }
            *(uint2*)(outh + off) = hw;
            *(uint2*)(outl + off) = lw;
        }
    }
}

// ====================================================================
// fp16 flash attention (UNCHANGED from round 11).
// ====================================================================
#define SM_BUF   0
#define BUF_SZ   40960
#define SM_PSH   163840
#define SM_F     196608
#define SM_MX    197632
#define SM_LS    198656
#define SM_LS2   199680
#define SM_MBAR  200192
#define ATTN_SMEM_BYTES 200448

__global__ void __launch_bounds__(512, 1) attn_mma(
    const float* __restrict__ x, float* __restrict__ out)
{
    extern __shared__ float sm[];
    const uint32_t sb = su32(sm);
    const int tid = threadIdx.x;
    const int w   = tid >> 5;
    const int qw  = w & 7;
    const int cg  = w >> 3;
    const int qp  = w & 3;
    const int ch  = w >> 2;
    const int l   = tid & 31;
    const int l4  = l >> 2;
    const int t   = l & 3;
    const int b   = blockIdx.y;
    const int qt  = blockIdx.x;
    const int q0  = qt * TQ;
    const uint32_t lane16 = (uint32_t)l * 16;
    const int barid = 1 + qw;

    const uint32_t mbD = sb + SM_MBAR;
    const uint32_t mbC = sb + SM_MBAR + 32;
    const uint32_t mxO = sb + SM_MX + (uint32_t)(((qw * 2 + cg) * 8 + l4) * 8);
    const uint32_t mxP = sb + SM_MX + (uint32_t)(((qw * 2 + (1 - cg)) * 8 + l4) * 8);

    if (tid == 0) {
#pragma unroll
        for (int i = 0; i < 4; i++) { MB_INIT(mbD + 8 * i, 1); MB_INIT(mbC + 8 * i, 16); }
    }
    __syncthreads();

    if (tid == 0) {
#pragma unroll
        for (int i = 0; i < 4; i++) {
            MB_EXPECT(mbD + 8 * i, 40960);
            bulkcp(sb + SM_BUF + i * BUF_SZ,
                   (const char*)g_k + ((size_t)(b * 64 + i) << 13), 8192, mbD + 8 * i);
            bulkcp(sb + SM_BUF + i * BUF_SZ + 8192,
                   (const char*)g_v + ((size_t)(b * 64 + i) << 15), 32768, mbD + 8 * i);
        }
    }

    uint32_t qh[2][4], ql[2][4];
    {
        const __half* qgm = g_q + ((size_t)(b * 32 + qt) << 13);
#pragma unroll
        for (int kg = 0; kg < 2; kg++) {
            uint4 v = *(const uint4*)(qgm + kg * 2048 + qw * 256 + l * 8);
            qh[kg][0] = v.x; qh[kg][1] = v.z; qh[kg][2] = v.y; qh[kg][3] = v.w;
            uint4 u2 = *(const uint4*)(qgm + 4096 + kg * 2048 + qw * 256 + l * 8);
            ql[kg][0] = u2.x; ql[kg][1] = u2.z; ql[kg][2] = u2.y; ql[kg][3] = u2.w;
        }
    }

    float o[16][4];
#pragma unroll
    for (int i = 0; i < 16; i++)
#pragma unroll
        for (int e = 0; e < 4; e++) o[i][e] = 0.f;
    float m0 = -1e30f, m1 = -1e30f, ls0 = 0.f, ls1 = 0.f;

    for (int tt = 0; tt < NT; tt++) {
        const int buf = tt & 3;
        const uint32_t kb = sb + SM_BUF + (uint32_t)buf * BUF_SZ;
        const uint32_t vb = kb + 8192;
        const uint32_t par = (uint32_t)((tt >> 2) & 1);
        const uint32_t pshB = sb + SM_PSH + (uint32_t)(tt & 1) * 16384;
        const uint32_t fB   = sb + SM_F   + (uint32_t)(tt & 1) * 512;
        mb_wait(mbD + 8 * buf, par);

        float sacc[4][4];
        const uint32_t kaBase = kb + (uint32_t)(cg * 2048) + lane16;
#pragma unroll
        for (int nt = 0; nt < 4; nt++) {
#pragma unroll
            for (int e = 0; e < 4; e++) sacc[nt][e] = 0.f;
            const uint32_t ka = kaBase + (uint32_t)(nt * 512);
            uint32_t h0, h1, h2, h3, g0, g1, g2, g3;
            lds128(h0, h1, h2, h3, ka);
            lds128(g0, g1, g2, g3, ka + 4096);
            mma_f16(sacc[nt], qh[0][0], qh[0][1], qh[0][2], qh[0][3], h0, h1);
            mma_f16(sacc[nt], qh[1][0], qh[1][1], qh[1][2], qh[1][3], h2, h3);
            mma_f16(sacc[nt], ql[0][0], ql[0][1], ql[0][2], ql[0][3], h0, h1);
            mma_f16(sacc[nt], ql[1][0], ql[1][1], ql[1][2], ql[1][3], h2, h3);
            mma_f16(sacc[nt], qh[0][0], qh[0][1], qh[0][2], qh[0][3], g0, g1);
            mma_f16(sacc[nt], qh[1][0], qh[1][1], qh[1][2], qh[1][3], g2, g3);
        }
        float mh0 = sacc[0][0], mh1 = sacc[0][2];
#pragma unroll
        for (int nt = 0; nt < 4; nt++) {
            mh0 = fmaxf(mh0, fmaxf(sacc[nt][0], sacc[nt][1]));
            mh1 = fmaxf(mh1, fmaxf(sacc[nt][2], sacc[nt][3]));
        }
        mh0 = fmaxf(mh0, __shfl_xor_sync(0xffffffffu, mh0, 1));
        mh0 = fmaxf(mh0, __shfl_xor_sync(0xffffffffu, mh0, 2));
        mh1 = fmaxf(mh1, __shfl_xor_sync(0xffffffffu, mh1, 1));
        mh1 = fmaxf(mh1, __shfl_xor_sync(0xffffffffu, mh1, 2));
        if (t == 0) sts_f2(mxO, mh0, mh1);
        BAR_PAIR(barid);
        float pm0, pm1;
        lds_f2(pm0, pm1, mxP);
        const float m0n = fmaxf(m0, fmaxf(mh0, pm0));
        const float m1n = fmaxf(m1, fmaxf(mh1, pm1));
        const float f0 = ex2f(m0 - m0n);
        const float f1 = ex2f(m1 - m1n);
        m0 = m0n; m1 = m1n;
        ls0 *= f0; ls1 *= f1;
        if (cg == 0 && t == 0) sts_f2(fB + (uint32_t)(qw * 64 + l4 * 8), f0, f1);

#pragma unroll
        for (int ul = 0; ul < 2; ul++) {
            const int u = cg * 2 + ul;
            uint32_t A0, A1, A2, A3;
            {
                float p0 = ex2f(sacc[2 * ul][0] - m0), p1 = ex2f(sacc[2 * ul][1] - m0);
                float p2 = ex2f(sacc[2 * ul][2] - m1), p3 = ex2f(sacc[2 * ul][3] - m1);
                A0 = packh2(p1, p0); A1 = packh2(p3, p2);
                p0 = ex2f(sacc[2 * ul + 1][0] - m0); p1 = ex2f(sacc[2 * ul + 1][1] - m0);
                p2 = ex2f(sacc[2 * ul + 1][2] - m1); p3 = ex2f(sacc[2 * ul + 1][3] - m1);
                A2 = packh2(p1, p0); A3 = packh2(p3, p2);
                ls0 += h2sum(A0) + h2sum(A2);
                ls1 += h2sum(A1) + h2sum(A3);
            }
            sts128(pshB + (uint32_t)(qw * 2048 + u * 512) + lane16, A0, A1, A2, A3);
        }
        __syncthreads();

        {
            float g0a, g1a, g0b, g1b;
            lds_f2(g0a, g1a, fB + (uint32_t)((2 * qp) * 64 + l4 * 8));
            lds_f2(g0b, g1b, fB + (uint32_t)((2 * qp + 1) * 64 + l4 * 8));
#pragma unroll
            for (int i = 0; i < 8; i++) {
                o[i][0] *= g0a; o[i][1] *= g0a; o[i][2] *= g1a; o[i][3] *= g1a;
            }
#pragma unroll
            for (int i = 8; i < 16; i++) {
                o[i][0] *= g0b; o[i][1] *= g0b; o[i][2] *= g1b; o[i][3] *= g1b;
            }
        }
#pragma unroll
        for (int u = 0; u < 4; u++) {
            uint32_t A0, A1, A2, A3, B0, B1, B2, B3;
            lds128(A0, A1, A2, A3, pshB + (uint32_t)((2 * qp) * 2048 + u * 512) + lane16);
            lds128(B0, B1, B2, B3, pshB + (uint32_t)((2 * qp + 1) * 2048 + u * 512) + lane16);
            uint32_t va = vb + (uint32_t)(u * 8192 + ch * 2048) + lane16;
#pragma unroll
            for (int p = 0; p < 4; p++) {
                uint32_t v0, v1, v2, v3;
                lds128(v0, v1, v2, v3, va);
                mma_f16(o[p * 2],         A0, A1, A2, A3, v0, v1);
                mma_f16(o[p * 2 + 1],     A0, A1, A2, A3, v2, v3);
                mma_f16(o[8 + p * 2],     B0, B1, B2, B3, v0, v1);
                mma_f16(o[8 + p * 2 + 1], B0, B1, B2, B3, v2, v3);
                va += 512;
            }
        }
        if (l == 0) MB_ARRIVE(mbC + 8 * buf);
        if (tid == 0 && tt + 4 < NT) {
            mb_wait(mbC + 8 * buf, par);
            MB_EXPECT(mbD + 8 * buf, 40960);
            bulkcp(kb, (const char*)g_k + ((size_t)(b * 64 + tt + 4) << 13), 8192, mbD + 8 * buf);
            bulkcp(vb, (const char*)g_v + ((size_t)(b * 64 + tt + 4) << 15), 32768, mbD + 8 * buf);
        }
    }

    ls0 += __shfl_xor_sync(0xffffffffu, ls0, 1);
    ls0 += __shfl_xor_sync(0xffffffffu, ls0, 2);
    ls1 += __shfl_xor_sync(0xffffffffu, ls1, 1);
    ls1 += __shfl_xor_sync(0xffffffffu, ls1, 2);
    if (t == 0) sts_f2(sb + SM_LS + (uint32_t)(((qw * 2 + cg) * 8 + l4) * 8), ls0, ls1);
    __syncthreads();
    {
        float p0, p1;
        lds_f2(p0, p1, sb + SM_LS + (uint32_t)(((qw * 2 + (1 - cg)) * 8 + l4) * 8));
        ls0 += p0; ls1 += p1;
    }
    if (cg == 0 && t == 0) {
        sm[(SM_LS2 >> 2) + qw * 16 + l4]     = ls0;
        sm[(SM_LS2 >> 2) + qw * 16 + l4 + 8] = ls1;
    }
    __syncthreads();
    float inv0a, inv1a, inv0b, inv1b;
    {
        const float* lsf = sm + (SM_LS2 >> 2);
        inv0a = 1.0f / lsf[(2 * qp) * 16 + l4];
        inv1a = 1.0f / lsf[(2 * qp) * 16 + l4 + 8];
        inv0b = 1.0f / lsf[(2 * qp + 1) * 16 + l4];
        inv1b = 1.0f / lsf[(2 * qp + 1) * 16 + l4 + 8];
    }

    float* stage = sm;
#pragma unroll 1
    for (int ch2 = 0; ch2 < 4; ch2++) {
        __syncthreads();
        if (ch == ch2) {
#pragma unroll
            for (int qb = 0; qb < 2; qb++) {
                const int q = (2 * qp + qb) * 16 + l4;
                const float i0 = qb ? inv0b : inv0a;
                const float i1 = qb ? inv1b : inv1a;
#pragma unroll
                for (int k = 0; k < 8; k++) {
                    const int i = qb * 8 + k;
                    const int cloc = k * 8 + 2 * t;
                    stage[cloc * 132 + q]           = o[i][0] * i0;
                    stage[(cloc + 1) * 132 + q]     = o[i][1] * i0;
                    stage[cloc * 132 + q + 8]       = o[i][2] * i1;
                    stage[(cloc + 1) * 132 + q + 8] = o[i][3] * i1;
                }
            }
        }
        __syncthreads();
        const int cloc2 = tid & 63;
        const int seg   = tid >> 6;
        const int cglob = ch2 * 64 + cloc2;
        const size_t gbase = ((size_t)(b * C_ + cglob)) * N_ + q0 + seg * 16;
        const float4* xs4 = (const float4*)(x + gbase);
        float4* os4 = (float4*)(out + gbase);
        const float* srow = stage + cloc2 * 132 + seg * 16;
#pragma unroll
        for (int i = 0; i < 4; i++) {
            float4 v = *(const float4*)(srow + 4 * i);
            float4 xv = xs4[i];
            float4 r;
            r.x = xv.x + v.x; r.y = xv.y + v.y; r.z = xv.z + v.z; r.w = xv.w + v.w;
            os4[i] = r;
        }
    }
}

// ====================================================================
extern "C" void kernel_launch(void* const* d_in, const int* in_sizes, int n_in,
                              void* d_out, int out_size)
{
    const float* x  = (const float*)d_in[0];
    const float* wq = (const float*)d_in[1];
    const float* bq = (const float*)d_in[2];
    const float* wk = (const float*)d_in[3];
    const float* bk = (const float*)d_in[4];
    const float* wv = (const float*)d_in[5];
    const float* bv = (const float*)d_in[6];
    float* out = (float*)d_out;

    cudaFuncSetAttribute(proj_mma, cudaFuncAttributeMaxDynamicSharedMemorySize, PROJ2_SMEM_BYTES);
    cudaFuncSetAttribute(attn_mma, cudaFuncAttributeMaxDynamicSharedMemorySize, ATTN_SMEM_BYTES);

    wprep<<<20, 512>>>(wv, wq, wk);
    proj_mma<<<dim3(64, 8), 640, PROJ2_SMEM_BYTES>>>(x, bq, bk, bv);
    attn_mma<<<dim3(N_ / TQ, B_), 512, ATTN_SMEM_BYTES>>>(x, out);
}